// round 1
// baseline (speedup 1.0000x reference)
#include <cuda_runtime.h>
#include <math.h>

#define SEQ    1560
#define DIM    1536
#define NH     12
#define HD     128
#define TOTAL  9360
#define START  7800
#define W_DIM  52
#define GIDX   5
#define CF     22
#define CHW    43   // CF + CH

// ---------------- scratch (no allocations allowed) ----------------
__device__ __align__(16) float g_q[SEQ * DIM];
__device__ __align__(16) float g_k[SEQ * DIM];
__device__ __align__(16) float g_v[SEQ * DIM];
__device__ __align__(16) float g_attn[SEQ * DIM];

// ---------------- SGEMM: C = A(MxK) @ W^T  (W: NxK, row-major) + bias --------
#define BM 128
#define BN 128
#define BK 16

__global__ __launch_bounds__(256) void sgemm_tn(
    const float* __restrict__ A, const float* __restrict__ Wt,
    const float* __restrict__ bias, float* __restrict__ C,
    int M, int N, int K)
{
    __shared__ float As[BK][BM + 4];
    __shared__ float Bs[BK][BN + 4];
    const int tid = threadIdx.x;
    const int bm = blockIdx.y * BM, bn = blockIdx.x * BN;
    const int tx = tid & 15, ty = tid >> 4;

    float acc[8][8];
#pragma unroll
    for (int i = 0; i < 8; i++)
#pragma unroll
        for (int j = 0; j < 8; j++) acc[i][j] = 0.f;

    for (int k0 = 0; k0 < K; k0 += BK) {
#pragma unroll
        for (int l = 0; l < 2; l++) {
            int idx = tid + l * 256;          // 0..511
            int m = idx >> 2, k4 = idx & 3;
            float4 v = make_float4(0.f, 0.f, 0.f, 0.f);
            int gm = bm + m;
            if (gm < M) v = *(const float4*)(A + (size_t)gm * K + k0 + k4 * 4);
            As[k4 * 4 + 0][m] = v.x; As[k4 * 4 + 1][m] = v.y;
            As[k4 * 4 + 2][m] = v.z; As[k4 * 4 + 3][m] = v.w;
        }
#pragma unroll
        for (int l = 0; l < 2; l++) {
            int idx = tid + l * 256;
            int n = idx >> 2, k4 = idx & 3;
            float4 v = make_float4(0.f, 0.f, 0.f, 0.f);
            int gn = bn + n;
            if (gn < N) v = *(const float4*)(Wt + (size_t)gn * K + k0 + k4 * 4);
            Bs[k4 * 4 + 0][n] = v.x; Bs[k4 * 4 + 1][n] = v.y;
            Bs[k4 * 4 + 2][n] = v.z; Bs[k4 * 4 + 3][n] = v.w;
        }
        __syncthreads();
#pragma unroll
        for (int k = 0; k < BK; k++) {
            float a[8], b[8];
#pragma unroll
            for (int i = 0; i < 8; i++) a[i] = As[k][ty * 8 + i];
#pragma unroll
            for (int j = 0; j < 8; j++) b[j] = Bs[k][tx * 8 + j];
#pragma unroll
            for (int i = 0; i < 8; i++)
#pragma unroll
                for (int j = 0; j < 8; j++) acc[i][j] += a[i] * b[j];
        }
        __syncthreads();
    }

#pragma unroll
    for (int i = 0; i < 8; i++) {
        int gm = bm + ty * 8 + i;
        if (gm >= M) continue;
#pragma unroll
        for (int j = 0; j < 8; j++) {
            int gn = bn + tx * 8 + j;
            if (gn < N) C[(size_t)gm * N + gn] = acc[i][j] + bias[gn];
        }
    }
}

// -------------- fused RMSNorm + RoPE (in-place, one block per row) -----------
__global__ __launch_bounds__(256) void norm_rope_kernel(
    float* __restrict__ buf, const float* __restrict__ w,
    const float* __restrict__ freqs)
{
    const int s = blockIdx.x;
    const int tid = threadIdx.x;
    float* row = buf + (size_t)s * DIM;

    float ss = 0.f;
    for (int i = tid; i < DIM; i += 256) { float v = row[i]; ss += v * v; }

    __shared__ float red[8];
#pragma unroll
    for (int o = 16; o > 0; o >>= 1) ss += __shfl_xor_sync(0xffffffffu, ss, o);
    if ((tid & 31) == 0) red[tid >> 5] = ss;
    __syncthreads();
    if (tid < 32) {
        float v = (tid < 8) ? red[tid] : 0.f;
#pragma unroll
        for (int o = 4; o > 0; o >>= 1) v += __shfl_xor_sync(0xffffffffu, v, o);
        if (tid == 0) red[0] = v;
    }
    __syncthreads();
    const float scale = rsqrtf(red[0] / (float)DIM + 1e-6f);

    const int h_idx = s / W_DIM;
    const int w_idx = s % W_DIM;

    for (int p = tid; p < DIM / 2; p += 256) {
        int j = p & 63;                 // pair index within head (0..63)
        int ridx;
        if (j < CF)        ridx = GIDX;    // frame part: f=1, f_idx=0 -> row GI
        else if (j < CHW)  ridx = h_idx;   // height part
        else               ridx = w_idx;   // width part
        float cs = freqs[(ridx * 64 + j) * 2 + 0];
        float sn = freqs[(ridx * 64 + j) * 2 + 1];
        float x0 = row[2 * p]     * scale * w[2 * p];
        float x1 = row[2 * p + 1] * scale * w[2 * p + 1];
        row[2 * p]     = x0 * cs - x1 * sn;
        row[2 * p + 1] = x0 * sn + x1 * cs;
    }
}

// ------------------- flash attention (fp32, online softmax) ------------------
// grid: (ceil(SEQ/32), NH), 256 threads. Warp w handles q rows [w*4, w*4+4),
// lane = key within the 32-key tile. O accumulators in registers (4 rows x 4 cols).
#define KS_STRIDE 132
#define SMEM_ATTN ((32*128 + 32*KS_STRIDE + 32*128 + 32*33) * 4)

__global__ __launch_bounds__(256) void attn_kernel(
    const float* __restrict__ kc, const float* __restrict__ vc)
{
    extern __shared__ float sm[];
    float* Qs = sm;                      // 32 x 128
    float* Ks = Qs + 32 * 128;           // 32 x 132 (padded: conflict-free row reads)
    float* Vs = Ks + 32 * KS_STRIDE;     // 32 x 128
    float* Ps = Vs + 32 * 128;           // 32 x 33

    const int head = blockIdx.y;
    const int q0 = blockIdx.x * 32;
    const int tid = threadIdx.x;
    const int lane = tid & 31;
    const int wid = tid >> 5;            // 0..7
    const int r0 = wid * 4;
    const float qscale = 0.08838834764831845f;  // 1/sqrt(128)

    // load + pre-scale Q tile
#pragma unroll
    for (int l = 0; l < 4; l++) {
        int idx = tid + l * 256;         // 0..1023
        int r = idx >> 5, c4 = idx & 31;
        int qs = q0 + r;
        float4 v = make_float4(0.f, 0.f, 0.f, 0.f);
        if (qs < SEQ) v = *(const float4*)(g_q + (size_t)qs * DIM + head * HD + c4 * 4);
        v.x *= qscale; v.y *= qscale; v.z *= qscale; v.w *= qscale;
        *(float4*)(Qs + r * 128 + c4 * 4) = v;
    }

    float m[4], lsum[4], o[4][4];
#pragma unroll
    for (int i = 0; i < 4; i++) {
        m[i] = -1e30f; lsum[i] = 0.f;
#pragma unroll
        for (int c = 0; c < 4; c++) o[i][c] = 0.f;
    }
    __syncthreads();

    for (int t0 = 0; t0 < TOTAL; t0 += 32) {
        // ---- load K/V tile (cold part from cache, hot part from scratch) ----
#pragma unroll
        for (int l = 0; l < 4; l++) {
            int idx = tid + l * 256;
            int r = idx >> 5, c4 = idx & 31;
            int t = t0 + r;
            float4 kv = make_float4(0.f, 0.f, 0.f, 0.f);
            float4 vv = make_float4(0.f, 0.f, 0.f, 0.f);
            if (t < TOTAL) {
                if (t < START) {
                    size_t off = ((size_t)t * NH + head) * HD + c4 * 4;
                    kv = *(const float4*)(kc + off);
                    vv = *(const float4*)(vc + off);
                } else {
                    size_t off = (size_t)(t - START) * DIM + head * HD + c4 * 4;
                    kv = *(const float4*)(g_k + off);
                    vv = *(const float4*)(g_v + off);
                }
            }
            *(float4*)(Ks + r * KS_STRIDE + c4 * 4) = kv;
            *(float4*)(Vs + r * 128 + c4 * 4) = vv;
        }
        __syncthreads();

        // ---- scores: this lane's key vs 4 q rows ----
        float s[4] = {0.f, 0.f, 0.f, 0.f};
#pragma unroll
        for (int c4 = 0; c4 < 32; c4++) {
            float4 kv = *(const float4*)(Ks + lane * KS_STRIDE + c4 * 4);
#pragma unroll
            for (int i = 0; i < 4; i++) {
                float4 qv = *(const float4*)(Qs + (r0 + i) * 128 + c4 * 4);
                s[i] += qv.x * kv.x + qv.y * kv.y + qv.z * kv.z + qv.w * kv.w;
            }
        }
        if (t0 + lane >= TOTAL) {
#pragma unroll
            for (int i = 0; i < 4; i++) s[i] = -1e30f;
        }

        // ---- online softmax (per-warp, per-row) ----
        float mx[4];
#pragma unroll
        for (int i = 0; i < 4; i++) mx[i] = s[i];
#pragma unroll
        for (int off = 16; off > 0; off >>= 1)
#pragma unroll
            for (int i = 0; i < 4; i++)
                mx[i] = fmaxf(mx[i], __shfl_xor_sync(0xffffffffu, mx[i], off));

        float p[4], rs[4];
#pragma unroll
        for (int i = 0; i < 4; i++) {
            float mn = fmaxf(m[i], mx[i]);
            p[i] = __expf(s[i] - mn);
            rs[i] = p[i];
            float alpha = __expf(m[i] - mn);
            lsum[i] *= alpha;
            m[i] = mn;
#pragma unroll
            for (int c = 0; c < 4; c++) o[i][c] *= alpha;
        }
#pragma unroll
        for (int off = 16; off > 0; off >>= 1)
#pragma unroll
            for (int i = 0; i < 4; i++)
                rs[i] += __shfl_xor_sync(0xffffffffu, rs[i], off);
#pragma unroll
        for (int i = 0; i < 4; i++) {
            lsum[i] += rs[i];
            Ps[(r0 + i) * 33 + lane] = p[i];
        }
        __syncwarp();

        // ---- O += P @ V ----
#pragma unroll
        for (int k = 0; k < 32; k++) {
            float4 v4 = *(const float4*)(Vs + k * 128 + lane * 4);
#pragma unroll
            for (int i = 0; i < 4; i++) {
                float pv = Ps[(r0 + i) * 33 + k];
                o[i][0] += pv * v4.x; o[i][1] += pv * v4.y;
                o[i][2] += pv * v4.z; o[i][3] += pv * v4.w;
            }
        }
        __syncthreads();
    }

#pragma unroll
    for (int i = 0; i < 4; i++) {
        int qs = q0 + r0 + i;
        if (qs < SEQ) {
            float inv = 1.f / lsum[i];
            float4 out = make_float4(o[i][0] * inv, o[i][1] * inv,
                                     o[i][2] * inv, o[i][3] * inv);
            *(float4*)(g_attn + (size_t)qs * DIM + head * HD + lane * 4) = out;
        }
    }
}

// ------------------------------- host launcher -------------------------------
extern "C" void kernel_launch(void* const* d_in, const int* in_sizes, int n_in,
                              void* d_out, int out_size)
{
    const float* x     = (const float*)d_in[0];
    const float* wq    = (const float*)d_in[1];
    const float* bq    = (const float*)d_in[2];
    const float* wk    = (const float*)d_in[3];
    const float* bk    = (const float*)d_in[4];
    const float* wv    = (const float*)d_in[5];
    const float* bv    = (const float*)d_in[6];
    const float* wo    = (const float*)d_in[7];
    const float* bo    = (const float*)d_in[8];
    const float* nq_w  = (const float*)d_in[9];
    const float* nk_w  = (const float*)d_in[10];
    const float* freqs = (const float*)d_in[11];
    const float* kc    = (const float*)d_in[12];
    const float* vc    = (const float*)d_in[13];
    float* out = (float*)d_out;

    float *qp, *kp, *vp, *ap;
    cudaGetSymbolAddress((void**)&qp, g_q);
    cudaGetSymbolAddress((void**)&kp, g_k);
    cudaGetSymbolAddress((void**)&vp, g_v);
    cudaGetSymbolAddress((void**)&ap, g_attn);

    dim3 gg(DIM / BN, (SEQ + BM - 1) / BM);   // (12, 13)

    sgemm_tn<<<gg, 256>>>(x, wq, bq, qp, SEQ, DIM, DIM);
    sgemm_tn<<<gg, 256>>>(x, wk, bk, kp, SEQ, DIM, DIM);
    sgemm_tn<<<gg, 256>>>(x, wv, bv, vp, SEQ, DIM, DIM);

    norm_rope_kernel<<<SEQ, 256>>>(qp, nq_w, freqs);
    norm_rope_kernel<<<SEQ, 256>>>(kp, nk_w, freqs);

    cudaFuncSetAttribute(attn_kernel,
                         cudaFuncAttributeMaxDynamicSharedMemorySize, SMEM_ATTN);
    attn_kernel<<<dim3((SEQ + 31) / 32, NH), 256, SMEM_ATTN>>>(kc, vc);

    sgemm_tn<<<gg, 256>>>(ap, wo, bo, out, SEQ, DIM, DIM);
}

// round 3
// speedup vs baseline: 4.8998x; 4.8998x over previous
#include <cuda_runtime.h>
#include <cuda_fp16.h>
#include <math.h>

#define SEQ    1560
#define DIM    1536
#define NH     12
#define HD     128
#define TOTAL  9360
#define START  7800
#define W_DIM  52
#define GIDX   5
#define CF     22
#define CHW    43

// ---------------- scratch (no allocations allowed) ----------------
__device__ __align__(16) float g_q[SEQ * DIM];
__device__ __align__(16) float g_k[SEQ * DIM];
__device__ __align__(16) float g_attn[SEQ * DIM];
__device__ __align__(16) __half g_qh[SEQ * DIM];
__device__ __align__(16) __half g_kh[TOTAL * DIM];
__device__ __align__(16) __half g_vh[TOTAL * DIM];

// ---------------- helpers ----------------
__device__ __forceinline__ unsigned f2tf32(float f) {
    unsigned r; asm("cvt.rna.tf32.f32 %0, %1;" : "=r"(r) : "f"(f)); return r;
}
__device__ __forceinline__ unsigned packh(float lo, float hi) {
    __half2 h = __floats2half2_rn(lo, hi);
    return *(unsigned*)&h;
}
__device__ __forceinline__ void mma_tf32(float* c, const unsigned* a, const unsigned* b) {
    asm volatile("mma.sync.aligned.m16n8k8.row.col.f32.tf32.tf32.f32 "
                 "{%0,%1,%2,%3}, {%4,%5,%6,%7}, {%8,%9}, {%0,%1,%2,%3};\n"
                 : "+f"(c[0]), "+f"(c[1]), "+f"(c[2]), "+f"(c[3])
                 : "r"(a[0]), "r"(a[1]), "r"(a[2]), "r"(a[3]), "r"(b[0]), "r"(b[1]));
}
__device__ __forceinline__ void mma_f16(float* c, unsigned a0, unsigned a1,
                                        unsigned a2, unsigned a3,
                                        unsigned b0, unsigned b1) {
    asm volatile("mma.sync.aligned.m16n8k16.row.col.f32.f16.f16.f32 "
                 "{%0,%1,%2,%3}, {%4,%5,%6,%7}, {%8,%9}, {%0,%1,%2,%3};\n"
                 : "+f"(c[0]), "+f"(c[1]), "+f"(c[2]), "+f"(c[3])
                 : "r"(a0), "r"(a1), "r"(a2), "r"(a3), "r"(b0), "r"(b1));
}

// ---------------- cold KV cache -> fp16 ----------------
__global__ __launch_bounds__(256) void conv_cold(
    const float* __restrict__ kc, const float* __restrict__ vc,
    __half* __restrict__ kh, __half* __restrict__ vh)
{
    int i = blockIdx.x * 256 + threadIdx.x;     // handles 4 elems
    const int N4 = START * DIM / 4;
    if (i >= N4) return;
    float4 a = ((const float4*)kc)[i];
    float4 b = ((const float4*)vc)[i];
    ((__half2*)kh)[2*i]   = __floats2half2_rn(a.x, a.y);
    ((__half2*)kh)[2*i+1] = __floats2half2_rn(a.z, a.w);
    ((__half2*)vh)[2*i]   = __floats2half2_rn(b.x, b.y);
    ((__half2*)vh)[2*i+1] = __floats2half2_rn(b.z, b.w);
}

// ---------------- tf32 tensor-core GEMM: C = A(MxK) @ W^T + bias -------------
// W row-major [N][K]. N=K=1536 fixed. Block 128x128, BK=32, 8 warps (2m x 4n).
#define ASTR 36

__global__ __launch_bounds__(256) void gemm_tf32(
    const float* __restrict__ A, const float* __restrict__ W,
    const float* __restrict__ bias, float* __restrict__ Cf,
    __half* __restrict__ Ch, int M)
{
    __shared__ float As[128][ASTR];
    __shared__ float Bs[128][ASTR];
    const int tid = threadIdx.x;
    const int bm = blockIdx.y * 128, bn = blockIdx.x * 128;
    const int wid = tid >> 5, lane = tid & 31;
    const int wm = (wid & 1) * 64, wn = (wid >> 1) * 32;
    const int gid = lane >> 2, tidg = lane & 3;

    float c[4][4][4];
#pragma unroll
    for (int mt = 0; mt < 4; mt++)
#pragma unroll
        for (int nt = 0; nt < 4; nt++)
#pragma unroll
            for (int i = 0; i < 4; i++) c[mt][nt][i] = 0.f;

    for (int k0 = 0; k0 < DIM; k0 += 32) {
#pragma unroll
        for (int l = 0; l < 4; l++) {
            int idx = tid + 256 * l;
            int r = idx >> 3, c4 = idx & 7;
            float4 v = make_float4(0.f, 0.f, 0.f, 0.f);
            if (bm + r < M) v = *(const float4*)(A + (size_t)(bm + r) * DIM + k0 + c4 * 4);
            As[r][c4*4+0] = __uint_as_float(f2tf32(v.x));
            As[r][c4*4+1] = __uint_as_float(f2tf32(v.y));
            As[r][c4*4+2] = __uint_as_float(f2tf32(v.z));
            As[r][c4*4+3] = __uint_as_float(f2tf32(v.w));
        }
#pragma unroll
        for (int l = 0; l < 4; l++) {
            int idx = tid + 256 * l;
            int r = idx >> 3, c4 = idx & 7;
            float4 v = *(const float4*)(W + (size_t)(bn + r) * DIM + k0 + c4 * 4);
            Bs[r][c4*4+0] = __uint_as_float(f2tf32(v.x));
            Bs[r][c4*4+1] = __uint_as_float(f2tf32(v.y));
            Bs[r][c4*4+2] = __uint_as_float(f2tf32(v.z));
            Bs[r][c4*4+3] = __uint_as_float(f2tf32(v.w));
        }
        __syncthreads();
#pragma unroll
        for (int ks = 0; ks < 4; ks++) {
            int kk = ks * 8;
            unsigned a[4][4], b[4][2];
#pragma unroll
            for (int mt = 0; mt < 4; mt++) {
                int row = wm + mt * 16;
                a[mt][0] = __float_as_uint(As[row + gid    ][kk + tidg]);
                a[mt][1] = __float_as_uint(As[row + gid + 8][kk + tidg]);
                a[mt][2] = __float_as_uint(As[row + gid    ][kk + tidg + 4]);
                a[mt][3] = __float_as_uint(As[row + gid + 8][kk + tidg + 4]);
            }
#pragma unroll
            for (int nt = 0; nt < 4; nt++) {
                int col = wn + nt * 8;
                b[nt][0] = __float_as_uint(Bs[col + gid][kk + tidg]);
                b[nt][1] = __float_as_uint(Bs[col + gid][kk + tidg + 4]);
            }
#pragma unroll
            for (int mt = 0; mt < 4; mt++)
#pragma unroll
                for (int nt = 0; nt < 4; nt++)
                    mma_tf32(c[mt][nt], a[mt], b[nt]);
        }
        __syncthreads();
    }

#pragma unroll
    for (int mt = 0; mt < 4; mt++) {
#pragma unroll
        for (int nt = 0; nt < 4; nt++) {
            int col = bn + wn + nt * 8 + 2 * tidg;
            float b0 = bias[col], b1 = bias[col + 1];
            int r = bm + wm + mt * 16 + gid;
            if (r < M) {
                float v0 = c[mt][nt][0] + b0, v1 = c[mt][nt][1] + b1;
                if (Cf) *(float2*)(Cf + (size_t)r * DIM + col) = make_float2(v0, v1);
                else *(__half2*)(Ch + (size_t)r * DIM + col) = __floats2half2_rn(v0, v1);
            }
            int r2 = r + 8;
            if (r2 < M) {
                float v0 = c[mt][nt][2] + b0, v1 = c[mt][nt][3] + b1;
                if (Cf) *(float2*)(Cf + (size_t)r2 * DIM + col) = make_float2(v0, v1);
                else *(__half2*)(Ch + (size_t)r2 * DIM + col) = __floats2half2_rn(v0, v1);
            }
        }
    }
}

// -------------- fused RMSNorm + RoPE -> fp16 (optionally pre-scaled) ----------
__global__ __launch_bounds__(256) void norm_rope_kernel(
    const float* __restrict__ in, const float* __restrict__ w,
    const float* __restrict__ freqs, __half* __restrict__ out,
    float outscale)
{
    const int s = blockIdx.x;
    const int tid = threadIdx.x;
    const float* row = in + (size_t)s * DIM;

    float ss = 0.f;
    for (int i = tid; i < DIM; i += 256) { float v = row[i]; ss += v * v; }
    __shared__ float red[8];
#pragma unroll
    for (int o = 16; o > 0; o >>= 1) ss += __shfl_xor_sync(0xffffffffu, ss, o);
    if ((tid & 31) == 0) red[tid >> 5] = ss;
    __syncthreads();
    if (tid < 32) {
        float v = (tid < 8) ? red[tid] : 0.f;
#pragma unroll
        for (int o = 4; o > 0; o >>= 1) v += __shfl_xor_sync(0xffffffffu, v, o);
        if (tid == 0) red[0] = v;
    }
    __syncthreads();
    const float scale = rsqrtf(red[0] / (float)DIM + 1e-6f);
    const int h_idx = s / W_DIM, w_idx = s % W_DIM;

    __half2* orow = (__half2*)(out + (size_t)s * DIM);
    for (int p = tid; p < DIM / 2; p += 256) {
        int j = p & 63;
        int ridx = (j < CF) ? GIDX : (j < CHW ? h_idx : w_idx);
        float cs = freqs[(ridx * 64 + j) * 2 + 0];
        float sn = freqs[(ridx * 64 + j) * 2 + 1];
        float x0 = row[2*p]   * scale * w[2*p];
        float x1 = row[2*p+1] * scale * w[2*p+1];
        orow[p] = __floats2half2_rn((x0 * cs - x1 * sn) * outscale,
                                    (x0 * sn + x1 * cs) * outscale);
    }
}

// ------------------- flash attention, fp16 mma.m16n8k16 ---------------------
// 1 block = 1 head x 64 q rows, 4 warps (16 q rows each). KV tiles of 64.
#define QSTR 136
#define VSTR 72
#define SMEM_ATT ((64*QSTR + 64*QSTR + 128*VSTR) * 2)

__global__ __launch_bounds__(128) void attn_mma(
    const __half* __restrict__ Kh, const __half* __restrict__ Vh,
    const __half* __restrict__ Qh, float* __restrict__ Og)
{
    extern __shared__ __half smb[];
    __half* Qs  = smb;                 // [64][QSTR]
    __half* Ks  = Qs + 64 * QSTR;      // [64][QSTR]
    __half* Vst = Ks + 64 * QSTR;      // [128][VSTR] transposed

    const int h = blockIdx.y, q0 = blockIdx.x * 64;
    const int tid = threadIdx.x, lane = tid & 31, wid = tid >> 5;
    const int gid = lane >> 2, tidg = lane & 3;

    // Q tile (pre-scaled by 1/sqrt(d) in norm_rope)
#pragma unroll
    for (int l = 0; l < 8; l++) {
        int idx = tid + 128 * l;
        int r = idx >> 4, cg = idx & 15;
        uint4 v = make_uint4(0, 0, 0, 0);
        if (q0 + r < SEQ) v = *(const uint4*)(Qh + (size_t)(q0 + r) * DIM + h * HD + cg * 8);
        *(uint4*)(Qs + r * QSTR + cg * 8) = v;
    }

    float m0 = -1e30f, m1 = -1e30f, l0 = 0.f, l1 = 0.f;
    float o[16][4];
#pragma unroll
    for (int t = 0; t < 16; t++)
#pragma unroll
        for (int i = 0; i < 4; i++) o[t][i] = 0.f;

    for (int t0 = 0; t0 < TOTAL; t0 += 64) {
        __syncthreads();   // protects Ks/Vst reuse (also orders first Q write)
#pragma unroll
        for (int l = 0; l < 8; l++) {
            int idx = tid + 128 * l;
            int r = idx >> 4, cg = idx & 15;
            uint4 v = make_uint4(0, 0, 0, 0);
            if (t0 + r < TOTAL) v = *(const uint4*)(Kh + (size_t)(t0 + r) * DIM + h * HD + cg * 8);
            *(uint4*)(Ks + r * QSTR + cg * 8) = v;
        }
        {
            int r = tid >> 1, half = tid & 1;
            int t = t0 + r;
#pragma unroll
            for (int i = 0; i < 8; i++) {
                int c0 = half * 64 + i * 8;
                uint4 v = make_uint4(0, 0, 0, 0);
                if (t < TOTAL) v = *(const uint4*)(Vh + (size_t)t * DIM + h * HD + c0);
                const __half* tp = (const __half*)&v;
#pragma unroll
                for (int j = 0; j < 8; j++) Vst[(c0 + j) * VSTR + r] = tp[j];
            }
        }
        __syncthreads();

        // ---- S = Q K^T ----
        float s[8][4];
#pragma unroll
        for (int nt = 0; nt < 8; nt++)
#pragma unroll
            for (int i = 0; i < 4; i++) s[nt][i] = 0.f;
#pragma unroll
        for (int j = 0; j < 8; j++) {
            int kk = j * 16;
            const __half* qb = Qs + (wid * 16) * QSTR + kk + 2 * tidg;
            unsigned a0 = *(const unsigned*)(qb + gid * QSTR);
            unsigned a1 = *(const unsigned*)(qb + (gid + 8) * QSTR);
            unsigned a2 = *(const unsigned*)(qb + gid * QSTR + 8);
            unsigned a3 = *(const unsigned*)(qb + (gid + 8) * QSTR + 8);
#pragma unroll
            for (int nt = 0; nt < 8; nt++) {
                const __half* kb = Ks + (nt * 8 + gid) * QSTR + kk + 2 * tidg;
                unsigned b0 = *(const unsigned*)kb;
                unsigned b1 = *(const unsigned*)(kb + 8);
                mma_f16(s[nt], a0, a1, a2, a3, b0, b1);
            }
        }

        // mask tail keys
        if (t0 + 64 > TOTAL) {
#pragma unroll
            for (int nt = 0; nt < 8; nt++) {
                int col = t0 + nt * 8 + 2 * tidg;
                if (col     >= TOTAL) { s[nt][0] = -1e30f; s[nt][2] = -1e30f; }
                if (col + 1 >= TOTAL) { s[nt][1] = -1e30f; s[nt][3] = -1e30f; }
            }
        }

        // ---- online softmax (rows gid and gid+8; quad = lanes sharing row) ----
        float mx0 = -1e30f, mx1 = -1e30f;
#pragma unroll
        for (int nt = 0; nt < 8; nt++) {
            mx0 = fmaxf(mx0, fmaxf(s[nt][0], s[nt][1]));
            mx1 = fmaxf(mx1, fmaxf(s[nt][2], s[nt][3]));
        }
#pragma unroll
        for (int off = 1; off < 4; off <<= 1) {
            mx0 = fmaxf(mx0, __shfl_xor_sync(0xffffffffu, mx0, off));
            mx1 = fmaxf(mx1, __shfl_xor_sync(0xffffffffu, mx1, off));
        }
        float mn0 = fmaxf(m0, mx0), mn1 = fmaxf(m1, mx1);
        float al0 = __expf(m0 - mn0), al1 = __expf(m1 - mn1);
        float rs0 = 0.f, rs1 = 0.f;
#pragma unroll
        for (int nt = 0; nt < 8; nt++) {
            s[nt][0] = __expf(s[nt][0] - mn0); rs0 += s[nt][0];
            s[nt][1] = __expf(s[nt][1] - mn0); rs0 += s[nt][1];
            s[nt][2] = __expf(s[nt][2] - mn1); rs1 += s[nt][2];
            s[nt][3] = __expf(s[nt][3] - mn1); rs1 += s[nt][3];
        }
#pragma unroll
        for (int off = 1; off < 4; off <<= 1) {
            rs0 += __shfl_xor_sync(0xffffffffu, rs0, off);
            rs1 += __shfl_xor_sync(0xffffffffu, rs1, off);
        }
        l0 = l0 * al0 + rs0; l1 = l1 * al1 + rs1;
        m0 = mn0; m1 = mn1;
#pragma unroll
        for (int t = 0; t < 16; t++) {
            o[t][0] *= al0; o[t][1] *= al0; o[t][2] *= al1; o[t][3] *= al1;
        }

        // ---- pack P into A fragments (FA2 layout identity) ----
        unsigned pa[4][4];
#pragma unroll
        for (int j = 0; j < 4; j++) {
            pa[j][0] = packh(s[2*j][0],   s[2*j][1]);
            pa[j][1] = packh(s[2*j][2],   s[2*j][3]);
            pa[j][2] = packh(s[2*j+1][0], s[2*j+1][1]);
            pa[j][3] = packh(s[2*j+1][2], s[2*j+1][3]);
        }

        // ---- O += P V ----
#pragma unroll
        for (int j = 0; j < 4; j++) {
            int kk = j * 16;
#pragma unroll
            for (int nt2 = 0; nt2 < 16; nt2++) {
                const __half* vb = Vst + (nt2 * 8 + gid) * VSTR + kk + 2 * tidg;
                unsigned b0 = *(const unsigned*)vb;
                unsigned b1 = *(const unsigned*)(vb + 8);
                mma_f16(o[nt2], pa[j][0], pa[j][1], pa[j][2], pa[j][3], b0, b1);
            }
        }
    }

    float inv0 = 1.f / l0, inv1 = 1.f / l1;
    int r = q0 + wid * 16 + gid;
#pragma unroll
    for (int nt2 = 0; nt2 < 16; nt2++) {
        int col = h * HD + nt2 * 8 + 2 * tidg;
        if (r < SEQ)
            *(float2*)(Og + (size_t)r * DIM + col) = make_float2(o[nt2][0] * inv0, o[nt2][1] * inv0);
        if (r + 8 < SEQ)
            *(float2*)(Og + (size_t)(r + 8) * DIM + col) = make_float2(o[nt2][2] * inv1, o[nt2][3] * inv1);
    }
}

// ------------------------------- host launcher -------------------------------
extern "C" void kernel_launch(void* const* d_in, const int* in_sizes, int n_in,
                              void* d_out, int out_size)
{
    const float* x     = (const float*)d_in[0];
    const float* wq    = (const float*)d_in[1];
    const float* bq    = (const float*)d_in[2];
    const float* wk    = (const float*)d_in[3];
    const float* bk    = (const float*)d_in[4];
    const float* wv    = (const float*)d_in[5];
    const float* bv    = (const float*)d_in[6];
    const float* wo    = (const float*)d_in[7];
    const float* bo    = (const float*)d_in[8];
    const float* nq_w  = (const float*)d_in[9];
    const float* nk_w  = (const float*)d_in[10];
    const float* freqs = (const float*)d_in[11];
    const float* kc    = (const float*)d_in[12];
    const float* vc    = (const float*)d_in[13];
    float* out = (float*)d_out;

    float *qp, *kp, *ap;
    __half *qh, *kh, *vh;
    cudaGetSymbolAddress((void**)&qp, g_q);
    cudaGetSymbolAddress((void**)&kp, g_k);
    cudaGetSymbolAddress((void**)&ap, g_attn);
    cudaGetSymbolAddress((void**)&qh, g_qh);
    cudaGetSymbolAddress((void**)&kh, g_kh);
    cudaGetSymbolAddress((void**)&vh, g_vh);

    // cold KV cache -> fp16
    conv_cold<<<(START * DIM / 4 + 255) / 256, 256>>>(kc, vc, kh, vh);

    dim3 gg(DIM / 128, (SEQ + 127) / 128);   // (12, 13)
    gemm_tf32<<<gg, 256>>>(x, wq, bq, qp, nullptr, SEQ);
    gemm_tf32<<<gg, 256>>>(x, wk, bk, kp, nullptr, SEQ);
    gemm_tf32<<<gg, 256>>>(x, wv, bv, nullptr, vh + (size_t)START * DIM, SEQ);

    const float qscale = 0.08838834764831845f;  // 1/sqrt(128)
    norm_rope_kernel<<<SEQ, 256>>>(qp, nq_w, freqs, qh, qscale);
    norm_rope_kernel<<<SEQ, 256>>>(kp, nk_w, freqs, kh + (size_t)START * DIM, 1.0f);

    cudaFuncSetAttribute(attn_mma, cudaFuncAttributeMaxDynamicSharedMemorySize, SMEM_ATT);
    attn_mma<<<dim3((SEQ + 63) / 64, NH), 128, SMEM_ATT>>>(kh, vh, qh, ap);

    gemm_tf32<<<gg, 256>>>(ap, wo, bo, out, nullptr, SEQ);
}

// round 4
// speedup vs baseline: 7.6116x; 1.5535x over previous
#include <cuda_runtime.h>
#include <cuda_fp16.h>
#include <math.h>

#define SEQ     1560
#define SEQ_PAD 1600
#define DIM     1536
#define NH      12
#define HD      128
#define TOTAL   9360
#define TOT_PAD 9408
#define START   7800
#define W_DIM   52
#define GIDX    5
#define CF      22
#define CHW     43

// ---------------- scratch (no allocations allowed) ----------------
__device__ __align__(16) float g_q[SEQ * DIM];
__device__ __align__(16) float g_k[SEQ * DIM];
__device__ __align__(16) float g_attn[SEQ * DIM];
__device__ __align__(16) float g_xr[SEQ * DIM];
__device__ __align__(16) float g_wr[4][DIM * DIM];     // wq,wk,wv,wo tf32-rounded
__device__ __align__(16) __half g_qh[SEQ_PAD * DIM];
__device__ __align__(16) __half g_kh[TOT_PAD * DIM];
__device__ __align__(16) __half g_vh[TOT_PAD * DIM];

// ---------------- asm helpers ----------------
__device__ __forceinline__ unsigned f2tf32(float f) {
    unsigned r; asm("cvt.rna.tf32.f32 %0, %1;" : "=r"(r) : "f"(f)); return r;
}
__device__ __forceinline__ unsigned packh(float lo, float hi) {
    __half2 h = __floats2half2_rn(lo, hi);
    return *(unsigned*)&h;
}
__device__ __forceinline__ unsigned sptr(const void* p) {
    return (unsigned)__cvta_generic_to_shared(p);
}
__device__ __forceinline__ void cp16(unsigned dst, const void* src) {
    asm volatile("cp.async.cg.shared.global [%0], [%1], 16;" :: "r"(dst), "l"(src));
}
__device__ __forceinline__ void cp16z(unsigned dst, const void* src, int sz) {
    asm volatile("cp.async.cg.shared.global [%0], [%1], 16, %2;" :: "r"(dst), "l"(src), "r"(sz));
}
__device__ __forceinline__ void cp_commit() { asm volatile("cp.async.commit_group;"); }
__device__ __forceinline__ void ldsm_x4(unsigned& r0, unsigned& r1, unsigned& r2, unsigned& r3, unsigned a) {
    asm volatile("ldmatrix.sync.aligned.m8n8.x4.shared.b16 {%0,%1,%2,%3}, [%4];"
                 : "=r"(r0), "=r"(r1), "=r"(r2), "=r"(r3) : "r"(a));
}
__device__ __forceinline__ void ldsm_x4t(unsigned& r0, unsigned& r1, unsigned& r2, unsigned& r3, unsigned a) {
    asm volatile("ldmatrix.sync.aligned.m8n8.x4.trans.shared.b16 {%0,%1,%2,%3}, [%4];"
                 : "=r"(r0), "=r"(r1), "=r"(r2), "=r"(r3) : "r"(a));
}
__device__ __forceinline__ void mma_tf32(float* c, const unsigned* a, const unsigned* b) {
    asm volatile("mma.sync.aligned.m16n8k8.row.col.f32.tf32.tf32.f32 "
                 "{%0,%1,%2,%3}, {%4,%5,%6,%7}, {%8,%9}, {%0,%1,%2,%3};\n"
                 : "+f"(c[0]), "+f"(c[1]), "+f"(c[2]), "+f"(c[3])
                 : "r"(a[0]), "r"(a[1]), "r"(a[2]), "r"(a[3]), "r"(b[0]), "r"(b[1]));
}
__device__ __forceinline__ void mma_f16(float* c, unsigned a0, unsigned a1,
                                        unsigned a2, unsigned a3,
                                        unsigned b0, unsigned b1) {
    asm volatile("mma.sync.aligned.m16n8k16.row.col.f32.f16.f16.f32 "
                 "{%0,%1,%2,%3}, {%4,%5,%6,%7}, {%8,%9}, {%0,%1,%2,%3};\n"
                 : "+f"(c[0]), "+f"(c[1]), "+f"(c[2]), "+f"(c[3])
                 : "r"(a0), "r"(a1), "r"(a2), "r"(a3), "r"(b0), "r"(b1));
}

// ---------------- prologue: round fp32 -> tf32 bits ----------------
__global__ __launch_bounds__(256) void round_tf32_k(
    const float* __restrict__ src, float* __restrict__ dst, int n4)
{
    int i = blockIdx.x * 256 + threadIdx.x;
    if (i >= n4) return;
    float4 v = ((const float4*)src)[i];
    v.x = __uint_as_float(f2tf32(v.x));
    v.y = __uint_as_float(f2tf32(v.y));
    v.z = __uint_as_float(f2tf32(v.z));
    v.w = __uint_as_float(f2tf32(v.w));
    ((float4*)dst)[i] = v;
}

// ---------------- cold KV cache -> fp16 ----------------
__global__ __launch_bounds__(256) void conv_cold(
    const float* __restrict__ kc, const float* __restrict__ vc,
    __half* __restrict__ kh, __half* __restrict__ vh)
{
    int i = blockIdx.x * 256 + threadIdx.x;
    const int N4 = START * DIM / 4;
    if (i >= N4) return;
    float4 a = ((const float4*)kc)[i];
    float4 b = ((const float4*)vc)[i];
    ((__half2*)kh)[2*i]   = __floats2half2_rn(a.x, a.y);
    ((__half2*)kh)[2*i+1] = __floats2half2_rn(a.z, a.w);
    ((__half2*)vh)[2*i]   = __floats2half2_rn(b.x, b.y);
    ((__half2*)vh)[2*i+1] = __floats2half2_rn(b.z, b.w);
}

// ---------------- zero the pad rows (tail-tile safety) ----------------
__global__ __launch_bounds__(256) void pad_zero(
    __half* __restrict__ qh, __half* __restrict__ kh, __half* __restrict__ vh)
{
    int i = blockIdx.x * 256 + threadIdx.x;
    const int nq = (SEQ_PAD - SEQ) * DIM;
    const int nk = (TOT_PAD - TOTAL) * DIM;
    __half z = __float2half(0.f);
    if (i < nq) qh[SEQ * DIM + i] = z;
    if (i < nk) { kh[TOTAL * DIM + i] = z; vh[TOTAL * DIM + i] = z; }
}

// ---------------- tf32 GEMM, cp.async double-buffered ----------------
// C = A(MxK) @ W^T + bias.  Inputs pre-rounded to tf32. Block 128x128, BK=32.
// MODE 0: fused QKV (blockIdx.x in [0,36), section = bx/12).  MODE 1: WO.
#define ASTR 36
#define G_STAGE (128 * ASTR)
#define GSMEM (4 * G_STAGE * 4)

template<int MODE>
__global__ __launch_bounds__(256) void gemm_tf32(
    const float* __restrict__ A,
    const float* __restrict__ W0, const float* __restrict__ W1, const float* __restrict__ W2,
    const float* __restrict__ bi0, const float* __restrict__ bi1, const float* __restrict__ bi2,
    float* __restrict__ outq, float* __restrict__ outk, __half* __restrict__ outv,
    float* __restrict__ outo, int M)
{
    extern __shared__ float smf[];
    // layout: As[2][128][ASTR], Bs[2][128][ASTR]
    const int tid = threadIdx.x;
    int sec = 0, bnl;
    if (MODE == 0) { sec = blockIdx.x / 12; bnl = (blockIdx.x % 12) * 128; }
    else           { bnl = blockIdx.x * 128; }
    const int bm = blockIdx.y * 128;
    const float* Wp   = (MODE == 1) ? W0 : (sec == 0 ? W0 : (sec == 1 ? W1 : W2));
    const float* bias = (MODE == 1) ? bi0 : (sec == 0 ? bi0 : (sec == 1 ? bi1 : bi2));

    const int wid = tid >> 5, lane = tid & 31;
    const int wm = (wid & 1) * 64, wn = (wid >> 1) * 32;
    const int gid = lane >> 2, tidg = lane & 3;

    const unsigned sA = sptr(smf);
    const unsigned sB = sA + 2 * G_STAGE * 4;
    const int lr = tid >> 3, lc = tid & 7;         // 32 rows x 8 chunks per 256-thread pass

    auto load_tile = [&](int st, int k0) {
#pragma unroll
        for (int l = 0; l < 4; l++) {
            int r = lr + l * 32;
            unsigned off = (unsigned)(st * G_STAGE + r * ASTR + lc * 4) * 4u;
            int gm = bm + r;
            int rowc = gm < M ? gm : (M - 1);
            cp16z(sA + off, A + (size_t)rowc * DIM + k0 + lc * 4, gm < M ? 16 : 0);
            cp16(sB + off, Wp + (size_t)(bnl + r) * DIM + k0 + lc * 4);
        }
        cp_commit();
    };

    float c[4][4][4];
#pragma unroll
    for (int mt = 0; mt < 4; mt++)
#pragma unroll
        for (int nt = 0; nt < 4; nt++)
#pragma unroll
            for (int i = 0; i < 4; i++) c[mt][nt][i] = 0.f;

    load_tile(0, 0);

    const int NIT = DIM / 32;   // 48
    for (int it = 0; it < NIT; it++) {
        if (it + 1 < NIT) {
            load_tile((it + 1) & 1, (it + 1) * 32);
            asm volatile("cp.async.wait_group 1;");
        } else {
            asm volatile("cp.async.wait_group 0;");
        }
        __syncthreads();

        const float* Asb = smf + (it & 1) * G_STAGE;
        const float* Bsb = smf + 2 * G_STAGE + (it & 1) * G_STAGE;
#pragma unroll
        for (int ks = 0; ks < 4; ks++) {
            int kk = ks * 8;
            unsigned a[4][4], b[4][2];
#pragma unroll
            for (int mt = 0; mt < 4; mt++) {
                int row = wm + mt * 16;
                a[mt][0] = __float_as_uint(Asb[(row + gid    ) * ASTR + kk + tidg]);
                a[mt][1] = __float_as_uint(Asb[(row + gid + 8) * ASTR + kk + tidg]);
                a[mt][2] = __float_as_uint(Asb[(row + gid    ) * ASTR + kk + tidg + 4]);
                a[mt][3] = __float_as_uint(Asb[(row + gid + 8) * ASTR + kk + tidg + 4]);
            }
#pragma unroll
            for (int nt = 0; nt < 4; nt++) {
                int col = wn + nt * 8;
                b[nt][0] = __float_as_uint(Bsb[(col + gid) * ASTR + kk + tidg]);
                b[nt][1] = __float_as_uint(Bsb[(col + gid) * ASTR + kk + tidg + 4]);
            }
#pragma unroll
            for (int mt = 0; mt < 4; mt++)
#pragma unroll
                for (int nt = 0; nt < 4; nt++)
                    mma_tf32(c[mt][nt], a[mt], b[nt]);
        }
        __syncthreads();
    }

#pragma unroll
    for (int mt = 0; mt < 4; mt++) {
#pragma unroll
        for (int nt = 0; nt < 4; nt++) {
            int col = bnl + wn + nt * 8 + 2 * tidg;
            float b0 = bias[col], b1 = bias[col + 1];
#pragma unroll
            for (int half = 0; half < 2; half++) {
                int r = bm + wm + mt * 16 + gid + half * 8;
                if (r >= M) continue;
                float v0 = c[mt][nt][2 * half]     + b0;
                float v1 = c[mt][nt][2 * half + 1] + b1;
                if (MODE == 1) {
                    *(float2*)(outo + (size_t)r * DIM + col) = make_float2(v0, v1);
                } else if (sec == 0) {
                    *(float2*)(outq + (size_t)r * DIM + col) = make_float2(v0, v1);
                } else if (sec == 1) {
                    *(float2*)(outk + (size_t)r * DIM + col) = make_float2(v0, v1);
                } else {
                    *(__half2*)(outv + (size_t)r * DIM + col) = __floats2half2_rn(v0, v1);
                }
            }
        }
    }
}

// -------------- fused RMSNorm + RoPE -> fp16 (pre-scaled) ----------
__global__ __launch_bounds__(256) void norm_rope_kernel(
    const float* __restrict__ in, const float* __restrict__ w,
    const float* __restrict__ freqs, __half* __restrict__ out,
    float outscale)
{
    const int s = blockIdx.x;
    const int tid = threadIdx.x;
    const float* row = in + (size_t)s * DIM;

    float ss = 0.f;
    for (int i = tid; i < DIM; i += 256) { float v = row[i]; ss += v * v; }
    __shared__ float red[8];
#pragma unroll
    for (int o = 16; o > 0; o >>= 1) ss += __shfl_xor_sync(0xffffffffu, ss, o);
    if ((tid & 31) == 0) red[tid >> 5] = ss;
    __syncthreads();
    if (tid < 32) {
        float v = (tid < 8) ? red[tid] : 0.f;
#pragma unroll
        for (int o = 4; o > 0; o >>= 1) v += __shfl_xor_sync(0xffffffffu, v, o);
        if (tid == 0) red[0] = v;
    }
    __syncthreads();
    const float scale = rsqrtf(red[0] / (float)DIM + 1e-6f);
    const int h_idx = s / W_DIM, w_idx = s % W_DIM;

    __half2* orow = (__half2*)(out + (size_t)s * DIM);
    for (int p = tid; p < DIM / 2; p += 256) {
        int j = p & 63;
        int ridx = (j < CF) ? GIDX : (j < CHW ? h_idx : w_idx);
        float cs = freqs[(ridx * 64 + j) * 2 + 0];
        float sn = freqs[(ridx * 64 + j) * 2 + 1];
        float x0 = row[2*p]   * scale * w[2*p];
        float x1 = row[2*p+1] * scale * w[2*p+1];
        orow[p] = __floats2half2_rn((x0 * cs - x1 * sn) * outscale,
                                    (x0 * sn + x1 * cs) * outscale);
    }
}

// ------------------- flash attention: ldmatrix + cp.async ---------------------
// 1 block = 1 head x 64 q rows, 4 warps (16 q rows each). KV tiles of 64, 2 stages.
#define QSTR 136
#define T_STAGE (64 * QSTR)                 // halves per stage
#define ATT_SMEM ((64 * QSTR + 4 * T_STAGE) * 2)
#define NKV_TILES (TOT_PAD / 64)            // 147

__global__ __launch_bounds__(128, 2) void attn_mma(
    const __half* __restrict__ Kh, const __half* __restrict__ Vh,
    const __half* __restrict__ Qh, float* __restrict__ Og)
{
    extern __shared__ __half smb[];
    __half* Qs = smb;                        // [64][QSTR]
    __half* Ks = Qs + 64 * QSTR;             // [2][64][QSTR]
    __half* Vs = Ks + 2 * T_STAGE;           // [2][64][QSTR]

    const int h = blockIdx.y, q0 = blockIdx.x * 64;
    const int tid = threadIdx.x, lane = tid & 31, wid = tid >> 5;
    const int gid = lane >> 2, tidg = lane & 3;

    const unsigned sQ = sptr(Qs);
    const unsigned sK = sptr(Ks);
    const unsigned sV = sptr(Vs);

    // per-thread ldmatrix offsets (bytes)
    const unsigned qoff = ((wid * 16 + (lane & 15)) * QSTR + (lane >> 4) * 8) * 2;
    const unsigned koff = (((lane >> 4) * 8 + (lane & 7)) * QSTR + ((lane >> 3) & 1) * 8) * 2;
    const unsigned voff = ((((lane >> 3) & 1) * 8 + (lane & 7)) * QSTR + (lane >> 4) * 8) * 2;

    // ---- load Q tile (synchronous, once; Qh is padded) ----
    {
        const int r = tid >> 1, cgb = (tid & 1) * 8;
#pragma unroll
        for (int i = 0; i < 8; i++) {
            int cg = cgb + i;
            *(uint4*)(Qs + r * QSTR + cg * 8) =
                *(const uint4*)(Qh + (size_t)(q0 + r) * DIM + h * HD + cg * 8);
        }
    }

    // ---- KV tile loader (cp.async; Kh/Vh padded) ----
    const int lr = tid >> 4, lc = tid & 15;
    auto load_kv = [&](int st, int t0) {
#pragma unroll
        for (int l = 0; l < 8; l++) {
            int r = lr + l * 8;
            unsigned off = (unsigned)(st * T_STAGE + r * QSTR + lc * 8) * 2u;
            const size_t g = (size_t)(t0 + r) * DIM + h * HD + lc * 8;
            cp16(sK + off, Kh + g);
            cp16(sV + off, Vh + g);
        }
        cp_commit();
    };

    load_kv(0, 0);
    __syncthreads();            // Q visible

    // ---- preload Q fragments (loop-invariant) ----
    unsigned qa[8][4];
#pragma unroll
    for (int j = 0; j < 8; j++)
        ldsm_x4(qa[j][0], qa[j][1], qa[j][2], qa[j][3], sQ + qoff + j * 32);

    float m0 = -1e30f, m1 = -1e30f, l0 = 0.f, l1 = 0.f;
    float o[16][4];
#pragma unroll
    for (int t = 0; t < 16; t++)
#pragma unroll
        for (int i = 0; i < 4; i++) o[t][i] = 0.f;

    for (int it = 0; it < NKV_TILES; it++) {
        if (it + 1 < NKV_TILES) {
            load_kv((it + 1) & 1, (it + 1) * 64);
            asm volatile("cp.async.wait_group 1;");
        } else {
            asm volatile("cp.async.wait_group 0;");
        }
        __syncthreads();

        const unsigned kb = sK + (unsigned)((it & 1) * T_STAGE * 2) + koff;
        const unsigned vb = sV + (unsigned)((it & 1) * T_STAGE * 2) + voff;

        // ---- S = Q K^T ----
        float s[8][4];
#pragma unroll
        for (int nt = 0; nt < 8; nt++)
#pragma unroll
            for (int i = 0; i < 4; i++) s[nt][i] = 0.f;
#pragma unroll
        for (int ntp = 0; ntp < 4; ntp++) {
#pragma unroll
            for (int j = 0; j < 8; j++) {
                unsigned b0, b1, b2, b3;
                ldsm_x4(b0, b1, b2, b3, kb + (ntp * 16 * QSTR + j * 16) * 2);
                mma_f16(s[2*ntp],   qa[j][0], qa[j][1], qa[j][2], qa[j][3], b0, b1);
                mma_f16(s[2*ntp+1], qa[j][0], qa[j][1], qa[j][2], qa[j][3], b2, b3);
            }
        }

        // tail mask (pad keys -> -inf); scores are in log2 domain
        if (it == NKV_TILES - 1) {
#pragma unroll
            for (int nt = 0; nt < 8; nt++) {
                int col = it * 64 + nt * 8 + 2 * tidg;
                if (col     >= TOTAL) { s[nt][0] = -1e30f; s[nt][2] = -1e30f; }
                if (col + 1 >= TOTAL) { s[nt][1] = -1e30f; s[nt][3] = -1e30f; }
            }
        }

        // ---- online softmax (base-2) ----
        float mx0 = -1e30f, mx1 = -1e30f;
#pragma unroll
        for (int nt = 0; nt < 8; nt++) {
            mx0 = fmaxf(mx0, fmaxf(s[nt][0], s[nt][1]));
            mx1 = fmaxf(mx1, fmaxf(s[nt][2], s[nt][3]));
        }
#pragma unroll
        for (int off = 1; off < 4; off <<= 1) {
            mx0 = fmaxf(mx0, __shfl_xor_sync(0xffffffffu, mx0, off));
            mx1 = fmaxf(mx1, __shfl_xor_sync(0xffffffffu, mx1, off));
        }
        float mn0 = fmaxf(m0, mx0), mn1 = fmaxf(m1, mx1);
        float al0 = exp2f(m0 - mn0), al1 = exp2f(m1 - mn1);
        float rs0 = 0.f, rs1 = 0.f;
#pragma unroll
        for (int nt = 0; nt < 8; nt++) {
            s[nt][0] = exp2f(s[nt][0] - mn0); rs0 += s[nt][0];
            s[nt][1] = exp2f(s[nt][1] - mn0); rs0 += s[nt][1];
            s[nt][2] = exp2f(s[nt][2] - mn1); rs1 += s[nt][2];
            s[nt][3] = exp2f(s[nt][3] - mn1); rs1 += s[nt][3];
        }
#pragma unroll
        for (int off = 1; off < 4; off <<= 1) {
            rs0 += __shfl_xor_sync(0xffffffffu, rs0, off);
            rs1 += __shfl_xor_sync(0xffffffffu, rs1, off);
        }
        l0 = l0 * al0 + rs0; l1 = l1 * al1 + rs1;
        m0 = mn0; m1 = mn1;
#pragma unroll
        for (int t = 0; t < 16; t++) {
            o[t][0] *= al0; o[t][1] *= al0; o[t][2] *= al1; o[t][3] *= al1;
        }

        // ---- pack P fragments ----
        unsigned pa[4][4];
#pragma unroll
        for (int j = 0; j < 4; j++) {
            pa[j][0] = packh(s[2*j][0],   s[2*j][1]);
            pa[j][1] = packh(s[2*j][2],   s[2*j][3]);
            pa[j][2] = packh(s[2*j+1][0], s[2*j+1][1]);
            pa[j][3] = packh(s[2*j+1][2], s[2*j+1][3]);
        }

        // ---- O += P V (ldmatrix.trans on row-major V) ----
#pragma unroll
        for (int j = 0; j < 4; j++) {
#pragma unroll
            for (int dp = 0; dp < 8; dp++) {
                unsigned b0, b1, b2, b3;
                ldsm_x4t(b0, b1, b2, b3, vb + (j * 16 * QSTR + dp * 16) * 2);
                mma_f16(o[2*dp],   pa[j][0], pa[j][1], pa[j][2], pa[j][3], b0, b1);
                mma_f16(o[2*dp+1], pa[j][0], pa[j][1], pa[j][2], pa[j][3], b2, b3);
            }
        }
        __syncthreads();
    }

    // ---- epilogue: write tf32-pre-rounded floats for the WO GEMM ----
    float inv0 = 1.f / l0, inv1 = 1.f / l1;
    int r = q0 + wid * 16 + gid;
#pragma unroll
    for (int nt2 = 0; nt2 < 16; nt2++) {
        int col = h * HD + nt2 * 8 + 2 * tidg;
        if (r < SEQ) {
            float2 v = make_float2(__uint_as_float(f2tf32(o[nt2][0] * inv0)),
                                   __uint_as_float(f2tf32(o[nt2][1] * inv0)));
            *(float2*)(Og + (size_t)r * DIM + col) = v;
        }
        if (r + 8 < SEQ) {
            float2 v = make_float2(__uint_as_float(f2tf32(o[nt2][2] * inv1)),
                                   __uint_as_float(f2tf32(o[nt2][3] * inv1)));
            *(float2*)(Og + (size_t)(r + 8) * DIM + col) = v;
        }
    }
}

// ------------------------------- host launcher -------------------------------
extern "C" void kernel_launch(void* const* d_in, const int* in_sizes, int n_in,
                              void* d_out, int out_size)
{
    const float* x     = (const float*)d_in[0];
    const float* wq    = (const float*)d_in[1];
    const float* bq    = (const float*)d_in[2];
    const float* wk    = (const float*)d_in[3];
    const float* bk    = (const float*)d_in[4];
    const float* wv    = (const float*)d_in[5];
    const float* bv    = (const float*)d_in[6];
    const float* wo    = (const float*)d_in[7];
    const float* bo    = (const float*)d_in[8];
    const float* nq_w  = (const float*)d_in[9];
    const float* nk_w  = (const float*)d_in[10];
    const float* freqs = (const float*)d_in[11];
    const float* kc    = (const float*)d_in[12];
    const float* vc    = (const float*)d_in[13];
    float* out = (float*)d_out;

    float *qp, *kp, *ap, *xr, *wr;
    __half *qh, *kh, *vh;
    cudaGetSymbolAddress((void**)&qp, g_q);
    cudaGetSymbolAddress((void**)&kp, g_k);
    cudaGetSymbolAddress((void**)&ap, g_attn);
    cudaGetSymbolAddress((void**)&xr, g_xr);
    cudaGetSymbolAddress((void**)&wr, g_wr);
    cudaGetSymbolAddress((void**)&qh, g_qh);
    cudaGetSymbolAddress((void**)&kh, g_kh);
    cudaGetSymbolAddress((void**)&vh, g_vh);

    const int WN4 = DIM * DIM / 4, XN4 = SEQ * DIM / 4;
    round_tf32_k<<<(WN4 + 255) / 256, 256>>>(wq, wr + 0 * DIM * DIM, WN4);
    round_tf32_k<<<(WN4 + 255) / 256, 256>>>(wk, wr + 1 * DIM * DIM, WN4);
    round_tf32_k<<<(WN4 + 255) / 256, 256>>>(wv, wr + 2 * DIM * DIM, WN4);
    round_tf32_k<<<(WN4 + 255) / 256, 256>>>(wo, wr + 3 * DIM * DIM, WN4);
    round_tf32_k<<<(XN4 + 255) / 256, 256>>>(x, xr, XN4);

    conv_cold<<<(START * DIM / 4 + 255) / 256, 256>>>(kc, vc, kh, vh);
    pad_zero<<<288, 256>>>(qh, kh, vh);

    cudaFuncSetAttribute(gemm_tf32<0>, cudaFuncAttributeMaxDynamicSharedMemorySize, GSMEM);
    cudaFuncSetAttribute(gemm_tf32<1>, cudaFuncAttributeMaxDynamicSharedMemorySize, GSMEM);
    cudaFuncSetAttribute(attn_mma, cudaFuncAttributeMaxDynamicSharedMemorySize, ATT_SMEM);

    // fused QKV
    gemm_tf32<0><<<dim3(36, 13), 256, GSMEM>>>(
        xr, wr + 0 * DIM * DIM, wr + 1 * DIM * DIM, wr + 2 * DIM * DIM,
        bq, bk, bv, qp, kp, vh + (size_t)START * DIM, nullptr, SEQ);

    const float qscale = 0.08838834764831845f * 1.4426950408889634f;  // 1/sqrt(d) * log2(e)
    norm_rope_kernel<<<SEQ, 256>>>(qp, nq_w, freqs, qh, qscale);
    norm_rope_kernel<<<SEQ, 256>>>(kp, nk_w, freqs, kh + (size_t)START * DIM, 1.0f);

    attn_mma<<<dim3(SEQ_PAD / 64, NH), 128, ATT_SMEM>>>(kh, vh, qh, ap);

    gemm_tf32<1><<<dim3(12, 13), 256, GSMEM>>>(
        ap, wr + 3 * DIM * DIM, nullptr, nullptr,
        bo, nullptr, nullptr, nullptr, nullptr, nullptr, out, SEQ);
}

// round 5
// speedup vs baseline: 7.6184x; 1.0009x over previous
#include <cuda_runtime.h>
#include <cuda_fp16.h>
#include <math.h>

#define SEQ     1560
#define SEQ_PAD 1600
#define DIM     1536
#define NH      12
#define HD      128
#define TOTAL   9360
#define TOT_PAD 9408
#define START   7800
#define W_DIM   52
#define GIDX    5
#define CF      22
#define CHW     43

// ---------------- scratch (no allocations allowed) ----------------
__device__ __align__(16) float g_q[SEQ * DIM];
__device__ __align__(16) float g_k[SEQ * DIM];
__device__ __align__(16) float g_attn[SEQ * DIM];
__device__ __align__(16) float g_xr[SEQ * DIM];
__device__ __align__(16) float g_wr[4][DIM * DIM];     // wq,wk,wv,wo tf32-rounded
__device__ __align__(16) __half g_qh[SEQ_PAD * DIM];
__device__ __align__(16) __half g_kh[TOT_PAD * DIM];
__device__ __align__(16) __half g_vh[TOT_PAD * DIM];

// ---------------- asm helpers ----------------
__device__ __forceinline__ unsigned f2tf32(float f) {
    unsigned r; asm("cvt.rna.tf32.f32 %0, %1;" : "=r"(r) : "f"(f)); return r;
}
__device__ __forceinline__ unsigned packh(float lo, float hi) {
    __half2 h = __floats2half2_rn(lo, hi);
    return *(unsigned*)&h;
}
__device__ __forceinline__ unsigned sptr(const void* p) {
    return (unsigned)__cvta_generic_to_shared(p);
}
__device__ __forceinline__ void cp16(unsigned dst, const void* src) {
    asm volatile("cp.async.cg.shared.global [%0], [%1], 16;" :: "r"(dst), "l"(src));
}
__device__ __forceinline__ void cp16z(unsigned dst, const void* src, int sz) {
    asm volatile("cp.async.cg.shared.global [%0], [%1], 16, %2;" :: "r"(dst), "l"(src), "r"(sz));
}
__device__ __forceinline__ void cp_commit() { asm volatile("cp.async.commit_group;"); }
__device__ __forceinline__ void ldsm_x4(unsigned& r0, unsigned& r1, unsigned& r2, unsigned& r3, unsigned a) {
    asm volatile("ldmatrix.sync.aligned.m8n8.x4.shared.b16 {%0,%1,%2,%3}, [%4];"
                 : "=r"(r0), "=r"(r1), "=r"(r2), "=r"(r3) : "r"(a));
}
__device__ __forceinline__ void ldsm_x4t(unsigned& r0, unsigned& r1, unsigned& r2, unsigned& r3, unsigned a) {
    asm volatile("ldmatrix.sync.aligned.m8n8.x4.trans.shared.b16 {%0,%1,%2,%3}, [%4];"
                 : "=r"(r0), "=r"(r1), "=r"(r2), "=r"(r3) : "r"(a));
}
__device__ __forceinline__ void mma_tf32(float* c, const unsigned* a, const unsigned* b) {
    asm volatile("mma.sync.aligned.m16n8k8.row.col.f32.tf32.tf32.f32 "
                 "{%0,%1,%2,%3}, {%4,%5,%6,%7}, {%8,%9}, {%0,%1,%2,%3};\n"
                 : "+f"(c[0]), "+f"(c[1]), "+f"(c[2]), "+f"(c[3])
                 : "r"(a[0]), "r"(a[1]), "r"(a[2]), "r"(a[3]), "r"(b[0]), "r"(b[1]));
}
__device__ __forceinline__ void mma_f16(float* c, unsigned a0, unsigned a1,
                                        unsigned a2, unsigned a3,
                                        unsigned b0, unsigned b1) {
    asm volatile("mma.sync.aligned.m16n8k16.row.col.f32.f16.f16.f32 "
                 "{%0,%1,%2,%3}, {%4,%5,%6,%7}, {%8,%9}, {%0,%1,%2,%3};\n"
                 : "+f"(c[0]), "+f"(c[1]), "+f"(c[2]), "+f"(c[3])
                 : "r"(a0), "r"(a1), "r"(a2), "r"(a3), "r"(b0), "r"(b1));
}

// ---------------- prologue: round fp32 -> tf32 bits ----------------
__global__ __launch_bounds__(256) void round_tf32_k(
    const float* __restrict__ src, float* __restrict__ dst, int n4)
{
    int i = blockIdx.x * 256 + threadIdx.x;
    if (i >= n4) return;
    float4 v = ((const float4*)src)[i];
    v.x = __uint_as_float(f2tf32(v.x));
    v.y = __uint_as_float(f2tf32(v.y));
    v.z = __uint_as_float(f2tf32(v.z));
    v.w = __uint_as_float(f2tf32(v.w));
    ((float4*)dst)[i] = v;
}

// ---------------- cold KV cache -> fp16 ----------------
__global__ __launch_bounds__(256) void conv_cold(
    const float* __restrict__ kc, const float* __restrict__ vc,
    __half* __restrict__ kh, __half* __restrict__ vh)
{
    int i = blockIdx.x * 256 + threadIdx.x;
    const int N4 = START * DIM / 4;
    if (i >= N4) return;
    float4 a = ((const float4*)kc)[i];
    float4 b = ((const float4*)vc)[i];
    ((__half2*)kh)[2*i]   = __floats2half2_rn(a.x, a.y);
    ((__half2*)kh)[2*i+1] = __floats2half2_rn(a.z, a.w);
    ((__half2*)vh)[2*i]   = __floats2half2_rn(b.x, b.y);
    ((__half2*)vh)[2*i+1] = __floats2half2_rn(b.z, b.w);
}

// ---------------- zero the pad rows (tail-tile safety) ----------------
__global__ __launch_bounds__(256) void pad_zero(
    __half* __restrict__ qh, __half* __restrict__ kh, __half* __restrict__ vh)
{
    int i = blockIdx.x * 256 + threadIdx.x;
    const int nq = (SEQ_PAD - SEQ) * DIM;
    const int nk = (TOT_PAD - TOTAL) * DIM;
    __half z = __float2half(0.f);
    if (i < nq) qh[SEQ * DIM + i] = z;
    if (i < nk) { kh[TOTAL * DIM + i] = z; vh[TOTAL * DIM + i] = z; }
}

// ---------------- tf32 GEMM, cp.async double-buffered ----------------
// C = A(MxK) @ W^T + bias.  Inputs pre-rounded to tf32. Block 128x128, BK=32.
// MODE 0: fused QKV (blockIdx.x in [0,36), section = bx/12).  MODE 1: WO.
#define ASTR 36
#define G_STAGE (128 * ASTR)
#define GSMEM (4 * G_STAGE * 4)

template<int MODE>
__global__ __launch_bounds__(256) void gemm_tf32(
    const float* __restrict__ A,
    const float* __restrict__ W0, const float* __restrict__ W1, const float* __restrict__ W2,
    const float* __restrict__ bi0, const float* __restrict__ bi1, const float* __restrict__ bi2,
    float* __restrict__ outq, float* __restrict__ outk, __half* __restrict__ outv,
    float* __restrict__ outo, int M)
{
    extern __shared__ float smf[];
    // layout: As[2][128][ASTR], Bs[2][128][ASTR]
    const int tid = threadIdx.x;
    int sec = 0, bnl;
    if (MODE == 0) { sec = blockIdx.x / 12; bnl = (blockIdx.x % 12) * 128; }
    else           { bnl = blockIdx.x * 128; }
    const int bm = blockIdx.y * 128;
    const float* Wp   = (MODE == 1) ? W0 : (sec == 0 ? W0 : (sec == 1 ? W1 : W2));
    const float* bias = (MODE == 1) ? bi0 : (sec == 0 ? bi0 : (sec == 1 ? bi1 : bi2));

    const int wid = tid >> 5, lane = tid & 31;
    const int wm = (wid & 1) * 64, wn = (wid >> 1) * 32;
    const int gid = lane >> 2, tidg = lane & 3;

    const unsigned sA = sptr(smf);
    const unsigned sB = sA + 2 * G_STAGE * 4;
    const int lr = tid >> 3, lc = tid & 7;         // 32 rows x 8 chunks per 256-thread pass

    auto load_tile = [&](int st, int k0) {
#pragma unroll
        for (int l = 0; l < 4; l++) {
            int r = lr + l * 32;
            unsigned off = (unsigned)(st * G_STAGE + r * ASTR + lc * 4) * 4u;
            int gm = bm + r;
            int rowc = gm < M ? gm : (M - 1);
            cp16z(sA + off, A + (size_t)rowc * DIM + k0 + lc * 4, gm < M ? 16 : 0);
            cp16(sB + off, Wp + (size_t)(bnl + r) * DIM + k0 + lc * 4);
        }
        cp_commit();
    };

    float c[4][4][4];
#pragma unroll
    for (int mt = 0; mt < 4; mt++)
#pragma unroll
        for (int nt = 0; nt < 4; nt++)
#pragma unroll
            for (int i = 0; i < 4; i++) c[mt][nt][i] = 0.f;

    load_tile(0, 0);

    const int NIT = DIM / 32;   // 48
    for (int it = 0; it < NIT; it++) {
        if (it + 1 < NIT) {
            load_tile((it + 1) & 1, (it + 1) * 32);
            asm volatile("cp.async.wait_group 1;");
        } else {
            asm volatile("cp.async.wait_group 0;");
        }
        __syncthreads();

        const float* Asb = smf + (it & 1) * G_STAGE;
        const float* Bsb = smf + 2 * G_STAGE + (it & 1) * G_STAGE;
#pragma unroll
        for (int ks = 0; ks < 4; ks++) {
            int kk = ks * 8;
            unsigned a[4][4], b[4][2];
#pragma unroll
            for (int mt = 0; mt < 4; mt++) {
                int row = wm + mt * 16;
                a[mt][0] = __float_as_uint(Asb[(row + gid    ) * ASTR + kk + tidg]);
                a[mt][1] = __float_as_uint(Asb[(row + gid + 8) * ASTR + kk + tidg]);
                a[mt][2] = __float_as_uint(Asb[(row + gid    ) * ASTR + kk + tidg + 4]);
                a[mt][3] = __float_as_uint(Asb[(row + gid + 8) * ASTR + kk + tidg + 4]);
            }
#pragma unroll
            for (int nt = 0; nt < 4; nt++) {
                int col = wn + nt * 8;
                b[nt][0] = __float_as_uint(Bsb[(col + gid) * ASTR + kk + tidg]);
                b[nt][1] = __float_as_uint(Bsb[(col + gid) * ASTR + kk + tidg + 4]);
            }
#pragma unroll
            for (int mt = 0; mt < 4; mt++)
#pragma unroll
                for (int nt = 0; nt < 4; nt++)
                    mma_tf32(c[mt][nt], a[mt], b[nt]);
        }
        __syncthreads();
    }

#pragma unroll
    for (int mt = 0; mt < 4; mt++) {
#pragma unroll
        for (int nt = 0; nt < 4; nt++) {
            int col = bnl + wn + nt * 8 + 2 * tidg;
            float b0 = bias[col], b1 = bias[col + 1];
#pragma unroll
            for (int half = 0; half < 2; half++) {
                int r = bm + wm + mt * 16 + gid + half * 8;
                if (r >= M) continue;
                float v0 = c[mt][nt][2 * half]     + b0;
                float v1 = c[mt][nt][2 * half + 1] + b1;
                if (MODE == 1) {
                    *(float2*)(outo + (size_t)r * DIM + col) = make_float2(v0, v1);
                } else if (sec == 0) {
                    *(float2*)(outq + (size_t)r * DIM + col) = make_float2(v0, v1);
                } else if (sec == 1) {
                    *(float2*)(outk + (size_t)r * DIM + col) = make_float2(v0, v1);
                } else {
                    *(__half2*)(outv + (size_t)r * DIM + col) = __floats2half2_rn(v0, v1);
                }
            }
        }
    }
}

// -------------- fused RMSNorm + RoPE -> fp16 (pre-scaled) ----------
__global__ __launch_bounds__(256) void norm_rope_kernel(
    const float* __restrict__ in, const float* __restrict__ w,
    const float* __restrict__ freqs, __half* __restrict__ out,
    float outscale)
{
    const int s = blockIdx.x;
    const int tid = threadIdx.x;
    const float* row = in + (size_t)s * DIM;

    float ss = 0.f;
    for (int i = tid; i < DIM; i += 256) { float v = row[i]; ss += v * v; }
    __shared__ float red[8];
#pragma unroll
    for (int o = 16; o > 0; o >>= 1) ss += __shfl_xor_sync(0xffffffffu, ss, o);
    if ((tid & 31) == 0) red[tid >> 5] = ss;
    __syncthreads();
    if (tid < 32) {
        float v = (tid < 8) ? red[tid] : 0.f;
#pragma unroll
        for (int o = 4; o > 0; o >>= 1) v += __shfl_xor_sync(0xffffffffu, v, o);
        if (tid == 0) red[0] = v;
    }
    __syncthreads();
    const float scale = rsqrtf(red[0] / (float)DIM + 1e-6f);
    const int h_idx = s / W_DIM, w_idx = s % W_DIM;

    __half2* orow = (__half2*)(out + (size_t)s * DIM);
    for (int p = tid; p < DIM / 2; p += 256) {
        int j = p & 63;
        int ridx = (j < CF) ? GIDX : (j < CHW ? h_idx : w_idx);
        float cs = freqs[(ridx * 64 + j) * 2 + 0];
        float sn = freqs[(ridx * 64 + j) * 2 + 1];
        float x0 = row[2*p]   * scale * w[2*p];
        float x1 = row[2*p+1] * scale * w[2*p+1];
        orow[p] = __floats2half2_rn((x0 * cs - x1 * sn) * outscale,
                                    (x0 * sn + x1 * cs) * outscale);
    }
}

// ------------------- flash attention: ldmatrix + cp.async ---------------------
// 1 block = 1 head x 64 q rows, 4 warps (16 q rows each). KV tiles of 64, 2 stages.
#define QSTR 136
#define T_STAGE (64 * QSTR)                 // halves per stage
#define ATT_SMEM ((64 * QSTR + 4 * T_STAGE) * 2)
#define NKV_TILES (TOT_PAD / 64)            // 147

__global__ __launch_bounds__(128, 2) void attn_mma(
    const __half* __restrict__ Kh, const __half* __restrict__ Vh,
    const __half* __restrict__ Qh, float* __restrict__ Og)
{
    extern __shared__ __half smb[];
    __half* Qs = smb;                        // [64][QSTR]
    __half* Ks = Qs + 64 * QSTR;             // [2][64][QSTR]
    __half* Vs = Ks + 2 * T_STAGE;           // [2][64][QSTR]

    const int h = blockIdx.y, q0 = blockIdx.x * 64;
    const int tid = threadIdx.x, lane = tid & 31, wid = tid >> 5;
    const int gid = lane >> 2, tidg = lane & 3;

    const unsigned sQ = sptr(Qs);
    const unsigned sK = sptr(Ks);
    const unsigned sV = sptr(Vs);

    // per-thread ldmatrix offsets (bytes)
    const unsigned qoff = ((wid * 16 + (lane & 15)) * QSTR + (lane >> 4) * 8) * 2;
    const unsigned koff = (((lane >> 4) * 8 + (lane & 7)) * QSTR + ((lane >> 3) & 1) * 8) * 2;
    const unsigned voff = ((((lane >> 3) & 1) * 8 + (lane & 7)) * QSTR + (lane >> 4) * 8) * 2;

    // ---- load Q tile (synchronous, once; Qh is padded) ----
    {
        const int r = tid >> 1, cgb = (tid & 1) * 8;
#pragma unroll
        for (int i = 0; i < 8; i++) {
            int cg = cgb + i;
            *(uint4*)(Qs + r * QSTR + cg * 8) =
                *(const uint4*)(Qh + (size_t)(q0 + r) * DIM + h * HD + cg * 8);
        }
    }

    // ---- KV tile loader (cp.async; Kh/Vh padded) ----
    const int lr = tid >> 4, lc = tid & 15;
    auto load_kv = [&](int st, int t0) {
#pragma unroll
        for (int l = 0; l < 8; l++) {
            int r = lr + l * 8;
            unsigned off = (unsigned)(st * T_STAGE + r * QSTR + lc * 8) * 2u;
            const size_t g = (size_t)(t0 + r) * DIM + h * HD + lc * 8;
            cp16(sK + off, Kh + g);
            cp16(sV + off, Vh + g);
        }
        cp_commit();
    };

    load_kv(0, 0);
    __syncthreads();            // Q visible

    // ---- preload Q fragments (loop-invariant) ----
    unsigned qa[8][4];
#pragma unroll
    for (int j = 0; j < 8; j++)
        ldsm_x4(qa[j][0], qa[j][1], qa[j][2], qa[j][3], sQ + qoff + j * 32);

    float m0 = -1e30f, m1 = -1e30f, l0 = 0.f, l1 = 0.f;
    float o[16][4];
#pragma unroll
    for (int t = 0; t < 16; t++)
#pragma unroll
        for (int i = 0; i < 4; i++) o[t][i] = 0.f;

    for (int it = 0; it < NKV_TILES; it++) {
        if (it + 1 < NKV_TILES) {
            load_kv((it + 1) & 1, (it + 1) * 64);
            asm volatile("cp.async.wait_group 1;");
        } else {
            asm volatile("cp.async.wait_group 0;");
        }
        __syncthreads();

        const unsigned kb = sK + (unsigned)((it & 1) * T_STAGE * 2) + koff;
        const unsigned vb = sV + (unsigned)((it & 1) * T_STAGE * 2) + voff;

        // ---- S = Q K^T ----
        float s[8][4];
#pragma unroll
        for (int nt = 0; nt < 8; nt++)
#pragma unroll
            for (int i = 0; i < 4; i++) s[nt][i] = 0.f;
#pragma unroll
        for (int ntp = 0; ntp < 4; ntp++) {
#pragma unroll
            for (int j = 0; j < 8; j++) {
                unsigned b0, b1, b2, b3;
                ldsm_x4(b0, b1, b2, b3, kb + (ntp * 16 * QSTR + j * 16) * 2);
                mma_f16(s[2*ntp],   qa[j][0], qa[j][1], qa[j][2], qa[j][3], b0, b1);
                mma_f16(s[2*ntp+1], qa[j][0], qa[j][1], qa[j][2], qa[j][3], b2, b3);
            }
        }

        // tail mask (pad keys -> -inf); scores are in log2 domain
        if (it == NKV_TILES - 1) {
#pragma unroll
            for (int nt = 0; nt < 8; nt++) {
                int col = it * 64 + nt * 8 + 2 * tidg;
                if (col     >= TOTAL) { s[nt][0] = -1e30f; s[nt][2] = -1e30f; }
                if (col + 1 >= TOTAL) { s[nt][1] = -1e30f; s[nt][3] = -1e30f; }
            }
        }

        // ---- online softmax (base-2) ----
        float mx0 = -1e30f, mx1 = -1e30f;
#pragma unroll
        for (int nt = 0; nt < 8; nt++) {
            mx0 = fmaxf(mx0, fmaxf(s[nt][0], s[nt][1]));
            mx1 = fmaxf(mx1, fmaxf(s[nt][2], s[nt][3]));
        }
#pragma unroll
        for (int off = 1; off < 4; off <<= 1) {
            mx0 = fmaxf(mx0, __shfl_xor_sync(0xffffffffu, mx0, off));
            mx1 = fmaxf(mx1, __shfl_xor_sync(0xffffffffu, mx1, off));
        }
        float mn0 = fmaxf(m0, mx0), mn1 = fmaxf(m1, mx1);
        float al0 = exp2f(m0 - mn0), al1 = exp2f(m1 - mn1);
        float rs0 = 0.f, rs1 = 0.f;
#pragma unroll
        for (int nt = 0; nt < 8; nt++) {
            s[nt][0] = exp2f(s[nt][0] - mn0); rs0 += s[nt][0];
            s[nt][1] = exp2f(s[nt][1] - mn0); rs0 += s[nt][1];
            s[nt][2] = exp2f(s[nt][2] - mn1); rs1 += s[nt][2];
            s[nt][3] = exp2f(s[nt][3] - mn1); rs1 += s[nt][3];
        }
#pragma unroll
        for (int off = 1; off < 4; off <<= 1) {
            rs0 += __shfl_xor_sync(0xffffffffu, rs0, off);
            rs1 += __shfl_xor_sync(0xffffffffu, rs1, off);
        }
        l0 = l0 * al0 + rs0; l1 = l1 * al1 + rs1;
        m0 = mn0; m1 = mn1;
#pragma unroll
        for (int t = 0; t < 16; t++) {
            o[t][0] *= al0; o[t][1] *= al0; o[t][2] *= al1; o[t][3] *= al1;
        }

        // ---- pack P fragments ----
        unsigned pa[4][4];
#pragma unroll
        for (int j = 0; j < 4; j++) {
            pa[j][0] = packh(s[2*j][0],   s[2*j][1]);
            pa[j][1] = packh(s[2*j][2],   s[2*j][3]);
            pa[j][2] = packh(s[2*j+1][0], s[2*j+1][1]);
            pa[j][3] = packh(s[2*j+1][2], s[2*j+1][3]);
        }

        // ---- O += P V (ldmatrix.trans on row-major V) ----
#pragma unroll
        for (int j = 0; j < 4; j++) {
#pragma unroll
            for (int dp = 0; dp < 8; dp++) {
                unsigned b0, b1, b2, b3;
                ldsm_x4t(b0, b1, b2, b3, vb + (j * 16 * QSTR + dp * 16) * 2);
                mma_f16(o[2*dp],   pa[j][0], pa[j][1], pa[j][2], pa[j][3], b0, b1);
                mma_f16(o[2*dp+1], pa[j][0], pa[j][1], pa[j][2], pa[j][3], b2, b3);
            }
        }
        __syncthreads();
    }

    // ---- epilogue: write tf32-pre-rounded floats for the WO GEMM ----
    float inv0 = 1.f / l0, inv1 = 1.f / l1;
    int r = q0 + wid * 16 + gid;
#pragma unroll
    for (int nt2 = 0; nt2 < 16; nt2++) {
        int col = h * HD + nt2 * 8 + 2 * tidg;
        if (r < SEQ) {
            float2 v = make_float2(__uint_as_float(f2tf32(o[nt2][0] * inv0)),
                                   __uint_as_float(f2tf32(o[nt2][1] * inv0)));
            *(float2*)(Og + (size_t)r * DIM + col) = v;
        }
        if (r + 8 < SEQ) {
            float2 v = make_float2(__uint_as_float(f2tf32(o[nt2][2] * inv1)),
                                   __uint_as_float(f2tf32(o[nt2][3] * inv1)));
            *(float2*)(Og + (size_t)(r + 8) * DIM + col) = v;
        }
    }
}

// ------------------------------- host launcher -------------------------------
extern "C" void kernel_launch(void* const* d_in, const int* in_sizes, int n_in,
                              void* d_out, int out_size)
{
    const float* x     = (const float*)d_in[0];
    const float* wq    = (const float*)d_in[1];
    const float* bq    = (const float*)d_in[2];
    const float* wk    = (const float*)d_in[3];
    const float* bk    = (const float*)d_in[4];
    const float* wv    = (const float*)d_in[5];
    const float* bv    = (const float*)d_in[6];
    const float* wo    = (const float*)d_in[7];
    const float* bo    = (const float*)d_in[8];
    const float* nq_w  = (const float*)d_in[9];
    const float* nk_w  = (const float*)d_in[10];
    const float* freqs = (const float*)d_in[11];
    const float* kc    = (const float*)d_in[12];
    const float* vc    = (const float*)d_in[13];
    float* out = (float*)d_out;

    float *qp, *kp, *ap, *xr, *wr;
    __half *qh, *kh, *vh;
    cudaGetSymbolAddress((void**)&qp, g_q);
    cudaGetSymbolAddress((void**)&kp, g_k);
    cudaGetSymbolAddress((void**)&ap, g_attn);
    cudaGetSymbolAddress((void**)&xr, g_xr);
    cudaGetSymbolAddress((void**)&wr, g_wr);
    cudaGetSymbolAddress((void**)&qh, g_qh);
    cudaGetSymbolAddress((void**)&kh, g_kh);
    cudaGetSymbolAddress((void**)&vh, g_vh);

    const int WN4 = DIM * DIM / 4, XN4 = SEQ * DIM / 4;
    round_tf32_k<<<(WN4 + 255) / 256, 256>>>(wq, wr + 0 * DIM * DIM, WN4);
    round_tf32_k<<<(WN4 + 255) / 256, 256>>>(wk, wr + 1 * DIM * DIM, WN4);
    round_tf32_k<<<(WN4 + 255) / 256, 256>>>(wv, wr + 2 * DIM * DIM, WN4);
    round_tf32_k<<<(WN4 + 255) / 256, 256>>>(wo, wr + 3 * DIM * DIM, WN4);
    round_tf32_k<<<(XN4 + 255) / 256, 256>>>(x, xr, XN4);

    conv_cold<<<(START * DIM / 4 + 255) / 256, 256>>>(kc, vc, kh, vh);
    pad_zero<<<288, 256>>>(qh, kh, vh);

    cudaFuncSetAttribute(gemm_tf32<0>, cudaFuncAttributeMaxDynamicSharedMemorySize, GSMEM);
    cudaFuncSetAttribute(gemm_tf32<1>, cudaFuncAttributeMaxDynamicSharedMemorySize, GSMEM);
    cudaFuncSetAttribute(attn_mma, cudaFuncAttributeMaxDynamicSharedMemorySize, ATT_SMEM);

    // fused QKV
    gemm_tf32<0><<<dim3(36, 13), 256, GSMEM>>>(
        xr, wr + 0 * DIM * DIM, wr + 1 * DIM * DIM, wr + 2 * DIM * DIM,
        bq, bk, bv, qp, kp, vh + (size_t)START * DIM, nullptr, SEQ);

    const float qscale = 0.08838834764831845f * 1.4426950408889634f;  // 1/sqrt(d) * log2(e)
    norm_rope_kernel<<<SEQ, 256>>>(qp, nq_w, freqs, qh, qscale);
    norm_rope_kernel<<<SEQ, 256>>>(kp, nk_w, freqs, kh + (size_t)START * DIM, 1.0f);

    attn_mma<<<dim3(SEQ_PAD / 64, NH), 128, ATT_SMEM>>>(kh, vh, qh, ap);

    gemm_tf32<1><<<dim3(12, 13), 256, GSMEM>>>(
        ap, wr + 3 * DIM * DIM, nullptr, nullptr,
        bo, nullptr, nullptr, nullptr, nullptr, nullptr, out, SEQ);
}

// round 7
// speedup vs baseline: 8.3577x; 1.0970x over previous
#include <cuda_runtime.h>
#include <cuda_fp16.h>
#include <math.h>

#define SEQ     1560
#define SEQ_PAD 1600
#define DIM     1536
#define NH      12
#define HD      128
#define TOTAL   9360
#define TOT_PAD 9408
#define START   7800
#define W_DIM   52
#define GIDX    5
#define CF      22
#define CHW     43

// ---------------- scratch (no allocations allowed) ----------------
__device__ __align__(16) float  g_q[SEQ * DIM];
__device__ __align__(16) float  g_k[SEQ * DIM];
__device__ __align__(16) float  g_attn[SEQ * DIM];
__device__ __align__(16) float  g_xr[SEQ * DIM];
__device__ __align__(16) float  g_wvr[DIM * DIM];
__device__ __align__(16) float  g_wor[DIM * DIM];
__device__ __align__(16) __half g_xh[SEQ * DIM];
__device__ __align__(16) __half g_whq[DIM * DIM];
__device__ __align__(16) __half g_whk[DIM * DIM];
__device__ __align__(16) __half g_qh[SEQ_PAD * DIM];
__device__ __align__(16) __half g_kh[TOT_PAD * DIM];
__device__ __align__(16) __half g_vh[TOT_PAD * DIM];

// ---------------- asm helpers ----------------
__device__ __forceinline__ unsigned f2tf32(float f) {
    unsigned r; asm("cvt.rna.tf32.f32 %0, %1;" : "=r"(r) : "f"(f)); return r;
}
__device__ __forceinline__ unsigned packh(float lo, float hi) {
    __half2 h = __floats2half2_rn(lo, hi);
    return *(unsigned*)&h;
}
__device__ __forceinline__ unsigned sptr(const void* p) {
    return (unsigned)__cvta_generic_to_shared(p);
}
__device__ __forceinline__ void cp16(unsigned dst, const void* src) {
    asm volatile("cp.async.cg.shared.global [%0], [%1], 16;" :: "r"(dst), "l"(src));
}
__device__ __forceinline__ void cp16z(unsigned dst, const void* src, int sz) {
    asm volatile("cp.async.cg.shared.global [%0], [%1], 16, %2;" :: "r"(dst), "l"(src), "r"(sz));
}
__device__ __forceinline__ void cp_commit() { asm volatile("cp.async.commit_group;"); }
__device__ __forceinline__ void ldsm_x4(unsigned& r0, unsigned& r1, unsigned& r2, unsigned& r3, unsigned a) {
    asm volatile("ldmatrix.sync.aligned.m8n8.x4.shared.b16 {%0,%1,%2,%3}, [%4];"
                 : "=r"(r0), "=r"(r1), "=r"(r2), "=r"(r3) : "r"(a));
}
__device__ __forceinline__ void ldsm_x4t(unsigned& r0, unsigned& r1, unsigned& r2, unsigned& r3, unsigned a) {
    asm volatile("ldmatrix.sync.aligned.m8n8.x4.trans.shared.b16 {%0,%1,%2,%3}, [%4];"
                 : "=r"(r0), "=r"(r1), "=r"(r2), "=r"(r3) : "r"(a));
}
__device__ __forceinline__ void mma_tf32(float* c, const unsigned* a, const unsigned* b) {
    asm volatile("mma.sync.aligned.m16n8k8.row.col.f32.tf32.tf32.f32 "
                 "{%0,%1,%2,%3}, {%4,%5,%6,%7}, {%8,%9}, {%0,%1,%2,%3};\n"
                 : "+f"(c[0]), "+f"(c[1]), "+f"(c[2]), "+f"(c[3])
                 : "r"(a[0]), "r"(a[1]), "r"(a[2]), "r"(a[3]), "r"(b[0]), "r"(b[1]));
}
__device__ __forceinline__ void mma_f16(float* c, unsigned a0, unsigned a1,
                                        unsigned a2, unsigned a3,
                                        unsigned b0, unsigned b1) {
    asm volatile("mma.sync.aligned.m16n8k16.row.col.f32.f16.f16.f32 "
                 "{%0,%1,%2,%3}, {%4,%5,%6,%7}, {%8,%9}, {%0,%1,%2,%3};\n"
                 : "+f"(c[0]), "+f"(c[1]), "+f"(c[2]), "+f"(c[3])
                 : "r"(a0), "r"(a1), "r"(a2), "r"(a3), "r"(b0), "r"(b1));
}

// ======================= fused prologue =======================
// Rounds wv,wo -> tf32; x -> tf32 + fp16; wq,wk -> fp16; cold KV -> fp16; pads.
__global__ __launch_bounds__(256) void prologue(
    const float* __restrict__ x,
    const float* __restrict__ wq, const float* __restrict__ wk,
    const float* __restrict__ wv, const float* __restrict__ wo,
    const float* __restrict__ kc, const float* __restrict__ vc)
{
    const int g = blockIdx.x * 256 + threadIdx.x;
    const int stride = gridDim.x * 256;

    const int WN4 = DIM * DIM / 4;
    const int XN4 = SEQ * DIM / 4;
    const int KN4 = START * DIM / 4;

    // wv, wo -> tf32
    for (int i = g; i < WN4; i += stride) {
        float4 a = ((const float4*)wv)[i];
        float4 b = ((const float4*)wo)[i];
        a.x = __uint_as_float(f2tf32(a.x)); a.y = __uint_as_float(f2tf32(a.y));
        a.z = __uint_as_float(f2tf32(a.z)); a.w = __uint_as_float(f2tf32(a.w));
        b.x = __uint_as_float(f2tf32(b.x)); b.y = __uint_as_float(f2tf32(b.y));
        b.z = __uint_as_float(f2tf32(b.z)); b.w = __uint_as_float(f2tf32(b.w));
        ((float4*)g_wvr)[i] = a;
        ((float4*)g_wor)[i] = b;
    }
    // x -> tf32 and fp16
    for (int i = g; i < XN4; i += stride) {
        float4 v = ((const float4*)x)[i];
        float4 r = make_float4(__uint_as_float(f2tf32(v.x)), __uint_as_float(f2tf32(v.y)),
                               __uint_as_float(f2tf32(v.z)), __uint_as_float(f2tf32(v.w)));
        ((float4*)g_xr)[i] = r;
        ((__half2*)g_xh)[2*i]   = __floats2half2_rn(v.x, v.y);
        ((__half2*)g_xh)[2*i+1] = __floats2half2_rn(v.z, v.w);
    }
    // wq, wk -> fp16
    for (int i = g; i < WN4; i += stride) {
        float4 a = ((const float4*)wq)[i];
        float4 b = ((const float4*)wk)[i];
        ((__half2*)g_whq)[2*i]   = __floats2half2_rn(a.x, a.y);
        ((__half2*)g_whq)[2*i+1] = __floats2half2_rn(a.z, a.w);
        ((__half2*)g_whk)[2*i]   = __floats2half2_rn(b.x, b.y);
        ((__half2*)g_whk)[2*i+1] = __floats2half2_rn(b.z, b.w);
    }
    // cold KV -> fp16
    for (int i = g; i < KN4; i += stride) {
        float4 a = ((const float4*)kc)[i];
        float4 b = ((const float4*)vc)[i];
        ((__half2*)g_kh)[2*i]   = __floats2half2_rn(a.x, a.y);
        ((__half2*)g_kh)[2*i+1] = __floats2half2_rn(a.z, a.w);
        ((__half2*)g_vh)[2*i]   = __floats2half2_rn(b.x, b.y);
        ((__half2*)g_vh)[2*i+1] = __floats2half2_rn(b.z, b.w);
    }
    // pads
    const int NQP = (SEQ_PAD - SEQ) * DIM / 8;
    const int NKP = (TOT_PAD - TOTAL) * DIM / 8;
    const uint4 z = make_uint4(0, 0, 0, 0);
    for (int i = g; i < NQP; i += stride) ((uint4*)(g_qh + SEQ * DIM))[i] = z;
    for (int i = g; i < NKP; i += stride) {
        ((uint4*)(g_kh + (size_t)TOTAL * DIM))[i] = z;
        ((uint4*)(g_vh + (size_t)TOTAL * DIM))[i] = z;
    }
}

// ================= fused QKV GEMM (mixed fp16 / tf32) =================
// grid (36, 13), 256 thr. bx<24: fp16 Q/K tiles. bx>=24: tf32 V tiles.
#define ASTR 36
#define G_STAGE (128 * ASTR)                 // floats per tf32 stage
#define GSMEM (4 * G_STAGE * 4)              // 73728 B
#define HSTR 40
#define H_STAGE (128 * HSTR)                 // halves per fp16 stage
#define NIT (DIM / 32)                       // 48

__global__ __launch_bounds__(256) void qkv_kernel(
    const __half* __restrict__ xh,
    const __half* __restrict__ whq, const __half* __restrict__ whk,
    const float* __restrict__ xr, const float* __restrict__ wvr,
    const float* __restrict__ bq, const float* __restrict__ bk, const float* __restrict__ bv,
    float* __restrict__ outq, float* __restrict__ outk, __half* __restrict__ outv)
{
    extern __shared__ __align__(16) char dyn[];
    const int tid = threadIdx.x;
    const int bm = blockIdx.y * 128;
    const int wid = tid >> 5, lane = tid & 31;
    const int wm = (wid & 1) * 64, wn = (wid >> 1) * 32;
    const int gid = lane >> 2, tidg = lane & 3;

    float c[4][4][4];
#pragma unroll
    for (int mt = 0; mt < 4; mt++)
#pragma unroll
        for (int nt = 0; nt < 4; nt++)
#pragma unroll
            for (int i = 0; i < 4; i++) c[mt][nt][i] = 0.f;

    if (blockIdx.x < 24) {
        // ---------------- fp16 path (Q or K projection) ----------------
        const int sec = blockIdx.x / 12;
        const int bnl = (blockIdx.x % 12) * 128;
        const __half* W    = sec ? whk : whq;
        const float* bias  = sec ? bk : bq;
        float* outp        = sec ? outk : outq;

        __half* smh = (__half*)dyn;
        const unsigned sA = sptr(smh);
        const unsigned sB = sA + 2 * H_STAGE * 2;

        // producer: 512 16B-chunks per operand per chunk-of-32; 2 each per thread
        auto load_tile = [&](int st, int k0) {
#pragma unroll
            for (int l = 0; l < 2; l++) {
                int idx = tid + 256 * l;
                int r = idx >> 2, ch = idx & 3;
                unsigned off = (unsigned)(st * H_STAGE + r * HSTR + ch * 8) * 2u;
                int gm = bm + r;
                int rowc = gm < SEQ ? gm : (SEQ - 1);
                cp16z(sA + off, xh + (size_t)rowc * DIM + k0 + ch * 8, gm < SEQ ? 16 : 0);
                cp16 (sB + off, W  + (size_t)(bnl + r) * DIM + k0 + ch * 8);
            }
            cp_commit();
        };

        const unsigned aoff = ((lane & 15) * HSTR + (lane >> 4) * 8) * 2;
        const unsigned boff = (((lane >> 4) * 8 + (lane & 7)) * HSTR + ((lane >> 3) & 1) * 8) * 2;

        load_tile(0, 0);
        for (int it = 0; it < NIT; it++) {
            if (it + 1 < NIT) {
                load_tile((it + 1) & 1, (it + 1) * 32);
                asm volatile("cp.async.wait_group 1;");
            } else {
                asm volatile("cp.async.wait_group 0;");
            }
            __syncthreads();

            const unsigned aB = sA + (unsigned)((it & 1) * H_STAGE * 2);
            const unsigned bB = sB + (unsigned)((it & 1) * H_STAGE * 2);
#pragma unroll
            for (int kf = 0; kf < 2; kf++) {
                unsigned a[4][4];
#pragma unroll
                for (int mt = 0; mt < 4; mt++)
                    ldsm_x4(a[mt][0], a[mt][1], a[mt][2], a[mt][3],
                            aB + (unsigned)(((wm + mt * 16) * HSTR + kf * 16) * 2) + aoff);
#pragma unroll
                for (int np = 0; np < 2; np++) {
                    unsigned b0, b1, b2, b3;
                    ldsm_x4(b0, b1, b2, b3,
                            bB + (unsigned)(((wn + np * 16) * HSTR + kf * 16) * 2) + boff);
#pragma unroll
                    for (int mt = 0; mt < 4; mt++) {
                        mma_f16(c[mt][2*np],   a[mt][0], a[mt][1], a[mt][2], a[mt][3], b0, b1);
                        mma_f16(c[mt][2*np+1], a[mt][0], a[mt][1], a[mt][2], a[mt][3], b2, b3);
                    }
                }
            }
            __syncthreads();
        }

        // epilogue -> float q/k
#pragma unroll
        for (int mt = 0; mt < 4; mt++) {
#pragma unroll
            for (int nt = 0; nt < 4; nt++) {
                int col = bnl + wn + nt * 8 + 2 * tidg;
                float b0 = bias[col], b1 = bias[col + 1];
#pragma unroll
                for (int half = 0; half < 2; half++) {
                    int r = bm + wm + mt * 16 + gid + half * 8;
                    if (r < SEQ)
                        *(float2*)(outp + (size_t)r * DIM + col) =
                            make_float2(c[mt][nt][2*half] + b0, c[mt][nt][2*half+1] + b1);
                }
            }
        }
    } else {
        // ---------------- tf32 path (V projection) ----------------
        const int bnl = (blockIdx.x - 24) * 128;
        float* smf = (float*)dyn;
        const unsigned sA = sptr(smf);
        const unsigned sB = sA + 2 * G_STAGE * 4;
        const int lr = tid >> 3, lc = tid & 7;

        auto load_tile = [&](int st, int k0) {
#pragma unroll
            for (int l = 0; l < 4; l++) {
                int r = lr + l * 32;
                unsigned off = (unsigned)(st * G_STAGE + r * ASTR + lc * 4) * 4u;
                int gm = bm + r;
                int rowc = gm < SEQ ? gm : (SEQ - 1);
                cp16z(sA + off, xr + (size_t)rowc * DIM + k0 + lc * 4, gm < SEQ ? 16 : 0);
                cp16 (sB + off, wvr + (size_t)(bnl + r) * DIM + k0 + lc * 4);
            }
            cp_commit();
        };

        load_tile(0, 0);
        for (int it = 0; it < NIT; it++) {
            if (it + 1 < NIT) {
                load_tile((it + 1) & 1, (it + 1) * 32);
                asm volatile("cp.async.wait_group 1;");
            } else {
                asm volatile("cp.async.wait_group 0;");
            }
            __syncthreads();

            const float* Asb = smf + (it & 1) * G_STAGE;
            const float* Bsb = smf + 2 * G_STAGE + (it & 1) * G_STAGE;
#pragma unroll
            for (int ks = 0; ks < 4; ks++) {
                int kk = ks * 8;
                unsigned a[4][4], b[4][2];
#pragma unroll
                for (int mt = 0; mt < 4; mt++) {
                    int row = wm + mt * 16;
                    a[mt][0] = __float_as_uint(Asb[(row + gid    ) * ASTR + kk + tidg]);
                    a[mt][1] = __float_as_uint(Asb[(row + gid + 8) * ASTR + kk + tidg]);
                    a[mt][2] = __float_as_uint(Asb[(row + gid    ) * ASTR + kk + tidg + 4]);
                    a[mt][3] = __float_as_uint(Asb[(row + gid + 8) * ASTR + kk + tidg + 4]);
                }
#pragma unroll
                for (int nt = 0; nt < 4; nt++) {
                    int col = wn + nt * 8;
                    b[nt][0] = __float_as_uint(Bsb[(col + gid) * ASTR + kk + tidg]);
                    b[nt][1] = __float_as_uint(Bsb[(col + gid) * ASTR + kk + tidg + 4]);
                }
#pragma unroll
                for (int mt = 0; mt < 4; mt++)
#pragma unroll
                    for (int nt = 0; nt < 4; nt++)
                        mma_tf32(c[mt][nt], a[mt], b[nt]);
            }
            __syncthreads();
        }

        // epilogue -> fp16 V (hot cache region)
#pragma unroll
        for (int mt = 0; mt < 4; mt++) {
#pragma unroll
            for (int nt = 0; nt < 4; nt++) {
                int col = bnl + wn + nt * 8 + 2 * tidg;
                float b0 = bv[col], b1 = bv[col + 1];
#pragma unroll
                for (int half = 0; half < 2; half++) {
                    int r = bm + wm + mt * 16 + gid + half * 8;
                    if (r < SEQ)
                        *(__half2*)(outv + (size_t)r * DIM + col) =
                            __floats2half2_rn(c[mt][nt][2*half] + b0, c[mt][nt][2*half+1] + b1);
                }
            }
        }
    }
}

// ================= WO GEMM (tf32, cp.async double-buffered) =================
__global__ __launch_bounds__(256) void wo_kernel(
    const float* __restrict__ A, const float* __restrict__ W,
    const float* __restrict__ bias, float* __restrict__ out)
{
    extern __shared__ __align__(16) char dyn[];
    float* smf = (float*)dyn;
    const int tid = threadIdx.x;
    const int bnl = blockIdx.x * 128, bm = blockIdx.y * 128;
    const int wid = tid >> 5, lane = tid & 31;
    const int wm = (wid & 1) * 64, wn = (wid >> 1) * 32;
    const int gid = lane >> 2, tidg = lane & 3;
    const unsigned sA = sptr(smf);
    const unsigned sB = sA + 2 * G_STAGE * 4;
    const int lr = tid >> 3, lc = tid & 7;

    auto load_tile = [&](int st, int k0) {
#pragma unroll
        for (int l = 0; l < 4; l++) {
            int r = lr + l * 32;
            unsigned off = (unsigned)(st * G_STAGE + r * ASTR + lc * 4) * 4u;
            int gm = bm + r;
            int rowc = gm < SEQ ? gm : (SEQ - 1);
            cp16z(sA + off, A + (size_t)rowc * DIM + k0 + lc * 4, gm < SEQ ? 16 : 0);
            cp16 (sB + off, W + (size_t)(bnl + r) * DIM + k0 + lc * 4);
        }
        cp_commit();
    };

    float c[4][4][4];
#pragma unroll
    for (int mt = 0; mt < 4; mt++)
#pragma unroll
        for (int nt = 0; nt < 4; nt++)
#pragma unroll
            for (int i = 0; i < 4; i++) c[mt][nt][i] = 0.f;

    load_tile(0, 0);
    for (int it = 0; it < NIT; it++) {
        if (it + 1 < NIT) {
            load_tile((it + 1) & 1, (it + 1) * 32);
            asm volatile("cp.async.wait_group 1;");
        } else {
            asm volatile("cp.async.wait_group 0;");
        }
        __syncthreads();

        const float* Asb = smf + (it & 1) * G_STAGE;
        const float* Bsb = smf + 2 * G_STAGE + (it & 1) * G_STAGE;
#pragma unroll
        for (int ks = 0; ks < 4; ks++) {
            int kk = ks * 8;
            unsigned a[4][4], b[4][2];
#pragma unroll
            for (int mt = 0; mt < 4; mt++) {
                int row = wm + mt * 16;
                a[mt][0] = __float_as_uint(Asb[(row + gid    ) * ASTR + kk + tidg]);
                a[mt][1] = __float_as_uint(Asb[(row + gid + 8) * ASTR + kk + tidg]);
                a[mt][2] = __float_as_uint(Asb[(row + gid    ) * ASTR + kk + tidg + 4]);
                a[mt][3] = __float_as_uint(Asb[(row + gid + 8) * ASTR + kk + tidg + 4]);
            }
#pragma unroll
            for (int nt = 0; nt < 4; nt++) {
                int col = wn + nt * 8;
                b[nt][0] = __float_as_uint(Bsb[(col + gid) * ASTR + kk + tidg]);
                b[nt][1] = __float_as_uint(Bsb[(col + gid) * ASTR + kk + tidg + 4]);
            }
#pragma unroll
            for (int mt = 0; mt < 4; mt++)
#pragma unroll
                for (int nt = 0; nt < 4; nt++)
                    mma_tf32(c[mt][nt], a[mt], b[nt]);
        }
        __syncthreads();
    }

#pragma unroll
    for (int mt = 0; mt < 4; mt++) {
#pragma unroll
        for (int nt = 0; nt < 4; nt++) {
            int col = bnl + wn + nt * 8 + 2 * tidg;
            float b0 = bias[col], b1 = bias[col + 1];
#pragma unroll
            for (int half = 0; half < 2; half++) {
                int r = bm + wm + mt * 16 + gid + half * 8;
                if (r < SEQ)
                    *(float2*)(out + (size_t)r * DIM + col) =
                        make_float2(c[mt][nt][2*half] + b0, c[mt][nt][2*half+1] + b1);
            }
        }
    }
}

// -------------- fused RMSNorm + RoPE for q AND k (blockIdx.y selects) --------
__global__ __launch_bounds__(256) void norm_rope2(
    const float* __restrict__ qin, const float* __restrict__ kin,
    const float* __restrict__ qw, const float* __restrict__ kw,
    const float* __restrict__ freqs,
    __half* __restrict__ qout, __half* __restrict__ kout, float qscale)
{
    const int s = blockIdx.x;
    const int which = blockIdx.y;
    const int tid = threadIdx.x;
    const float* row = (which ? kin : qin) + (size_t)s * DIM;
    const float* w   = which ? kw : qw;
    __half* out      = which ? kout : qout;
    const float outscale = which ? 1.0f : qscale;

    float ss = 0.f;
    for (int i = tid; i < DIM; i += 256) { float v = row[i]; ss += v * v; }
    __shared__ float red[8];
#pragma unroll
    for (int o = 16; o > 0; o >>= 1) ss += __shfl_xor_sync(0xffffffffu, ss, o);
    if ((tid & 31) == 0) red[tid >> 5] = ss;
    __syncthreads();
    if (tid < 32) {
        float v = (tid < 8) ? red[tid] : 0.f;
#pragma unroll
        for (int o = 4; o > 0; o >>= 1) v += __shfl_xor_sync(0xffffffffu, v, o);
        if (tid == 0) red[0] = v;
    }
    __syncthreads();
    const float scale = rsqrtf(red[0] / (float)DIM + 1e-6f);
    const int h_idx = s / W_DIM, w_idx = s % W_DIM;

    __half2* orow = (__half2*)(out + (size_t)s * DIM);
    for (int p = tid; p < DIM / 2; p += 256) {
        int j = p & 63;
        int ridx = (j < CF) ? GIDX : (j < CHW ? h_idx : w_idx);
        float cs = freqs[(ridx * 64 + j) * 2 + 0];
        float sn = freqs[(ridx * 64 + j) * 2 + 1];
        float x0 = row[2*p]   * scale * w[2*p];
        float x1 = row[2*p+1] * scale * w[2*p+1];
        orow[p] = __floats2half2_rn((x0 * cs - x1 * sn) * outscale,
                                    (x0 * sn + x1 * cs) * outscale);
    }
}

// ------------------- flash attention: ldmatrix + cp.async ---------------------
#define QSTR 136
#define T_STAGE (64 * QSTR)
#define ATT_SMEM ((64 * QSTR + 4 * T_STAGE) * 2)
#define NKV_TILES (TOT_PAD / 64)

__global__ __launch_bounds__(128, 2) void attn_mma(
    const __half* __restrict__ Kh, const __half* __restrict__ Vh,
    const __half* __restrict__ Qh, float* __restrict__ Og)
{
    extern __shared__ __half smb[];
    __half* Qs = smb;
    __half* Ks = Qs + 64 * QSTR;
    __half* Vs = Ks + 2 * T_STAGE;

    const int h = blockIdx.y, q0 = blockIdx.x * 64;
    const int tid = threadIdx.x, lane = tid & 31, wid = tid >> 5;
    const int gid = lane >> 2, tidg = lane & 3;

    const unsigned sQ = sptr(Qs);
    const unsigned sK = sptr(Ks);
    const unsigned sV = sptr(Vs);

    const unsigned qoff = ((wid * 16 + (lane & 15)) * QSTR + (lane >> 4) * 8) * 2;
    const unsigned koff = (((lane >> 4) * 8 + (lane & 7)) * QSTR + ((lane >> 3) & 1) * 8) * 2;
    const unsigned voff = ((((lane >> 3) & 1) * 8 + (lane & 7)) * QSTR + (lane >> 4) * 8) * 2;

    {
        const int r = tid >> 1, cgb = (tid & 1) * 8;
#pragma unroll
        for (int i = 0; i < 8; i++) {
            int cg = cgb + i;
            *(uint4*)(Qs + r * QSTR + cg * 8) =
                *(const uint4*)(Qh + (size_t)(q0 + r) * DIM + h * HD + cg * 8);
        }
    }

    const int lr = tid >> 4, lc = tid & 15;
    auto load_kv = [&](int st, int t0) {
#pragma unroll
        for (int l = 0; l < 8; l++) {
            int r = lr + l * 8;
            unsigned off = (unsigned)(st * T_STAGE + r * QSTR + lc * 8) * 2u;
            const size_t g = (size_t)(t0 + r) * DIM + h * HD + lc * 8;
            cp16(sK + off, Kh + g);
            cp16(sV + off, Vh + g);
        }
        cp_commit();
    };

    load_kv(0, 0);
    __syncthreads();

    unsigned qa[8][4];
#pragma unroll
    for (int j = 0; j < 8; j++)
        ldsm_x4(qa[j][0], qa[j][1], qa[j][2], qa[j][3], sQ + qoff + j * 32);

    float m0 = -1e30f, m1 = -1e30f, l0 = 0.f, l1 = 0.f;
    float o[16][4];
#pragma unroll
    for (int t = 0; t < 16; t++)
#pragma unroll
        for (int i = 0; i < 4; i++) o[t][i] = 0.f;

    for (int it = 0; it < NKV_TILES; it++) {
        if (it + 1 < NKV_TILES) {
            load_kv((it + 1) & 1, (it + 1) * 64);
            asm volatile("cp.async.wait_group 1;");
        } else {
            asm volatile("cp.async.wait_group 0;");
        }
        __syncthreads();

        const unsigned kb = sK + (unsigned)((it & 1) * T_STAGE * 2) + koff;
        const unsigned vb = sV + (unsigned)((it & 1) * T_STAGE * 2) + voff;

        float s[8][4];
#pragma unroll
        for (int nt = 0; nt < 8; nt++)
#pragma unroll
            for (int i = 0; i < 4; i++) s[nt][i] = 0.f;
#pragma unroll
        for (int ntp = 0; ntp < 4; ntp++) {
#pragma unroll
            for (int j = 0; j < 8; j++) {
                unsigned b0, b1, b2, b3;
                ldsm_x4(b0, b1, b2, b3, kb + (ntp * 16 * QSTR + j * 16) * 2);
                mma_f16(s[2*ntp],   qa[j][0], qa[j][1], qa[j][2], qa[j][3], b0, b1);
                mma_f16(s[2*ntp+1], qa[j][0], qa[j][1], qa[j][2], qa[j][3], b2, b3);
            }
        }

        if (it == NKV_TILES - 1) {
#pragma unroll
            for (int nt = 0; nt < 8; nt++) {
                int col = it * 64 + nt * 8 + 2 * tidg;
                if (col     >= TOTAL) { s[nt][0] = -1e30f; s[nt][2] = -1e30f; }
                if (col + 1 >= TOTAL) { s[nt][1] = -1e30f; s[nt][3] = -1e30f; }
            }
        }

        float mx0 = -1e30f, mx1 = -1e30f;
#pragma unroll
        for (int nt = 0; nt < 8; nt++) {
            mx0 = fmaxf(mx0, fmaxf(s[nt][0], s[nt][1]));
            mx1 = fmaxf(mx1, fmaxf(s[nt][2], s[nt][3]));
        }
#pragma unroll
        for (int off = 1; off < 4; off <<= 1) {
            mx0 = fmaxf(mx0, __shfl_xor_sync(0xffffffffu, mx0, off));
            mx1 = fmaxf(mx1, __shfl_xor_sync(0xffffffffu, mx1, off));
        }
        float mn0 = fmaxf(m0, mx0), mn1 = fmaxf(m1, mx1);
        float al0 = exp2f(m0 - mn0), al1 = exp2f(m1 - mn1);
        float rs0 = 0.f, rs1 = 0.f;
#pragma unroll
        for (int nt = 0; nt < 8; nt++) {
            s[nt][0] = exp2f(s[nt][0] - mn0); rs0 += s[nt][0];
            s[nt][1] = exp2f(s[nt][1] - mn0); rs0 += s[nt][1];
            s[nt][2] = exp2f(s[nt][2] - mn1); rs1 += s[nt][2];
            s[nt][3] = exp2f(s[nt][3] - mn1); rs1 += s[nt][3];
        }
#pragma unroll
        for (int off = 1; off < 4; off <<= 1) {
            rs0 += __shfl_xor_sync(0xffffffffu, rs0, off);
            rs1 += __shfl_xor_sync(0xffffffffu, rs1, off);
        }
        l0 = l0 * al0 + rs0; l1 = l1 * al1 + rs1;
        m0 = mn0; m1 = mn1;
#pragma unroll
        for (int t = 0; t < 16; t++) {
            o[t][0] *= al0; o[t][1] *= al0; o[t][2] *= al1; o[t][3] *= al1;
        }

        unsigned pa[4][4];
#pragma unroll
        for (int j = 0; j < 4; j++) {
            pa[j][0] = packh(s[2*j][0],   s[2*j][1]);
            pa[j][1] = packh(s[2*j][2],   s[2*j][3]);
            pa[j][2] = packh(s[2*j+1][0], s[2*j+1][1]);
            pa[j][3] = packh(s[2*j+1][2], s[2*j+1][3]);
        }

#pragma unroll
        for (int j = 0; j < 4; j++) {
#pragma unroll
            for (int dp = 0; dp < 8; dp++) {
                unsigned b0, b1, b2, b3;
                ldsm_x4t(b0, b1, b2, b3, vb + (j * 16 * QSTR + dp * 16) * 2);
                mma_f16(o[2*dp],   pa[j][0], pa[j][1], pa[j][2], pa[j][3], b0, b1);
                mma_f16(o[2*dp+1], pa[j][0], pa[j][1], pa[j][2], pa[j][3], b2, b3);
            }
        }
        __syncthreads();
    }

    float inv0 = 1.f / l0, inv1 = 1.f / l1;
    int r = q0 + wid * 16 + gid;
#pragma unroll
    for (int nt2 = 0; nt2 < 16; nt2++) {
        int col = h * HD + nt2 * 8 + 2 * tidg;
        if (r < SEQ) {
            float2 v = make_float2(__uint_as_float(f2tf32(o[nt2][0] * inv0)),
                                   __uint_as_float(f2tf32(o[nt2][1] * inv0)));
            *(float2*)(Og + (size_t)r * DIM + col) = v;
        }
        if (r + 8 < SEQ) {
            float2 v = make_float2(__uint_as_float(f2tf32(o[nt2][2] * inv1)),
                                   __uint_as_float(f2tf32(o[nt2][3] * inv1)));
            *(float2*)(Og + (size_t)(r + 8) * DIM + col) = v;
        }
    }
}

// ------------------------------- host launcher -------------------------------
extern "C" void kernel_launch(void* const* d_in, const int* in_sizes, int n_in,
                              void* d_out, int out_size)
{
    const float* x     = (const float*)d_in[0];
    const float* wq    = (const float*)d_in[1];
    const float* bq    = (const float*)d_in[2];
    const float* wk    = (const float*)d_in[3];
    const float* bk    = (const float*)d_in[4];
    const float* wv    = (const float*)d_in[5];
    const float* bv    = (const float*)d_in[6];
    const float* wo    = (const float*)d_in[7];
    const float* bo    = (const float*)d_in[8];
    const float* nq_w  = (const float*)d_in[9];
    const float* nk_w  = (const float*)d_in[10];
    const float* freqs = (const float*)d_in[11];
    const float* kc    = (const float*)d_in[12];
    const float* vc    = (const float*)d_in[13];
    float* out = (float*)d_out;

    float *qp, *kp, *ap, *xr, *wvr, *wor;
    __half *qh, *kh, *vh, *xh, *whq, *whk;
    cudaGetSymbolAddress((void**)&qp,  g_q);
    cudaGetSymbolAddress((void**)&kp,  g_k);
    cudaGetSymbolAddress((void**)&ap,  g_attn);
    cudaGetSymbolAddress((void**)&xr,  g_xr);
    cudaGetSymbolAddress((void**)&wvr, g_wvr);
    cudaGetSymbolAddress((void**)&wor, g_wor);
    cudaGetSymbolAddress((void**)&qh,  g_qh);
    cudaGetSymbolAddress((void**)&kh,  g_kh);
    cudaGetSymbolAddress((void**)&vh,  g_vh);
    cudaGetSymbolAddress((void**)&xh,  g_xh);
    cudaGetSymbolAddress((void**)&whq, g_whq);
    cudaGetSymbolAddress((void**)&whk, g_whk);

    cudaFuncSetAttribute(qkv_kernel, cudaFuncAttributeMaxDynamicSharedMemorySize, GSMEM);
    cudaFuncSetAttribute(wo_kernel,  cudaFuncAttributeMaxDynamicSharedMemorySize, GSMEM);
    cudaFuncSetAttribute(attn_mma,   cudaFuncAttributeMaxDynamicSharedMemorySize, ATT_SMEM);

    prologue<<<1216, 256>>>(x, wq, wk, wv, wo, kc, vc);

    qkv_kernel<<<dim3(36, 13), 256, GSMEM>>>(
        xh, whq, whk, xr, wvr, bq, bk, bv,
        qp, kp, vh + (size_t)START * DIM);

    const float qscale = 0.08838834764831845f * 1.4426950408889634f;  // 1/sqrt(d)*log2(e)
    norm_rope2<<<dim3(SEQ, 2), 256>>>(qp, kp, nq_w, nk_w, freqs,
                                      qh, kh + (size_t)START * DIM, qscale);

    attn_mma<<<dim3(SEQ_PAD / 64, NH), 128, ATT_SMEM>>>(kh, vh, qh, ap);

    wo_kernel<<<dim3(12, 13), 256, GSMEM>>>(ap, wor, bo, out);
}